// round 1
// baseline (speedup 1.0000x reference)
#include <cuda_runtime.h>
#include <math.h>

#define NN 32
#define CC 32
#define MM 10
#define DD 16
#define SS 196
#define BBF 6272.0f
#define EPSF 1e-6f
#define LAM_INIT 0.001f
#define LAM_ROUT 0.001f
#define LN2PI 1.8378770664093453f

// ---- persistent scratch (no cudaMalloc allowed) ----
__device__ float g_S1[NN*MM*DD];
__device__ float g_S2[NN*MM*DD];
__device__ float g_R [NN*MM];
__device__ float g_A1[NN*MM*DD];
__device__ float g_A2[NN*MM*DD];
__device__ float g_mu[NN*MM*DD];
__device__ float g_i2s[NN*MM*DD];   // 1/(2*sigma)
__device__ float g_K [NN*MM];       // -0.5*sum_d log(sigma) - 8*LN2PI + log(a)
__device__ float g_a [NN*MM];

__global__ void k_init()
{
    int i = blockIdx.x * blockDim.x + threadIdx.x;
    if (i < NN*MM*DD) { g_S1[i] = 0.f; g_S2[i] = 0.f; }
}

// ---------------- pass A: S1 = sum_i V, S2 = sum_i V^2 ----------------
__global__ __launch_bounds__(224) void k_passA(const float* __restrict__ l,
                                               const float* __restrict__ w)
{
    const int c = blockIdx.x, n = blockIdx.y;
    __shared__ float w_sh[MM*DD];
    __shared__ float acc1[MM*DD], acc2[MM*DD];
    const int tid = threadIdx.x;
    if (tid < MM*DD) {
        w_sh[tid] = w[c*MM*DD + tid];
        acc1[tid] = 0.f; acc2[tid] = 0.f;
    }
    __syncthreads();

    const bool act = tid < SS;
    float lv[16];
    const float* lbase = l + (size_t)(n*CC + c)*DD*SS + (act ? tid : 0);
#pragma unroll
    for (int d = 0; d < 16; d++) lv[d] = act ? lbase[d*SS] : 0.f;

#pragma unroll
    for (int m = 0; m < MM; m++) {
        float wr[16];
#pragma unroll
        for (int k = 0; k < 16; k++) wr[k] = w_sh[m*16 + k];
#pragma unroll
        for (int p = 0; p < 4; p++) {
            float a0 = lv[4*p+0], a1 = lv[4*p+1], a2 = lv[4*p+2], a3 = lv[4*p+3];
#pragma unroll
            for (int r = 0; r < 4; r++) {
                float v  = fmaf(a0, wr[r], fmaf(a1, wr[4+r], fmaf(a2, wr[8+r], a3*wr[12+r])));
                float v2 = v * v;
#pragma unroll
                for (int o = 16; o > 0; o >>= 1) {
                    v  += __shfl_xor_sync(0xffffffffu, v,  o);
                    v2 += __shfl_xor_sync(0xffffffffu, v2, o);
                }
                if ((tid & 31) == 0) {
                    atomicAdd(&acc1[m*16 + p*4 + r], v);
                    atomicAdd(&acc2[m*16 + p*4 + r], v2);
                }
            }
        }
    }
    __syncthreads();
    if (tid < MM*DD) {
        atomicAdd(&g_S1[n*MM*DD + tid], acc1[tid]);
        atomicAdd(&g_S2[n*MM*DD + tid], acc2[tid]);
    }
}

// ---------------- epilogue A: init a, iter0 M-step, E-constants ----------------
__global__ void k_epiA(const float* __restrict__ g,
                       const float* __restrict__ beta_a,
                       const float* __restrict__ beta_u)
{
    const int n = blockIdx.x;
    const int t = threadIdx.x;           // 160 threads
    const int m = t >> 4, d = t & 15;

    float S1 = g_S1[n*160 + t], S2 = g_S2[n*160 + t];
    float gv = g[(n*MM + m)*DD + d];

    // init sigma = sum_i (V-g)^2 + EPS
    float sig0 = S2 - 2.f*gv*S1 + BBF*gv*gv + EPSF;
    float sl = logf(sig0);
#pragma unroll
    for (int o = 8; o > 0; o >>= 1) sl += __shfl_xor_sync(0xffffffffu, sl, o);

    float ba = beta_a[m], bu = beta_u[m];
    float a0 = 1.f / (1.f + expf(-(LAM_INIT * (ba - 16.f*bu - 0.5f*sl))));

    // iter 0 M-step with uniform r = a0/10
    float rsum  = BBF * a0 * 0.1f;
    float coeff = (a0 * 0.1f) / (rsum + EPSF);
    float mu    = coeff * S1;
    float sig   = coeff * (S2 - 2.f*mu*S1 + BBF*mu*mu) + EPSF;
    float lg = logf(sig);
    float sl2 = lg;
#pragma unroll
    for (int o = 8; o > 0; o >>= 1) sl2 += __shfl_xor_sync(0xffffffffu, sl2, o);

    float logit = LAM_ROUT * (ba - rsum * (16.f*bu + 0.5f*sl2));
    float a1 = 1.f / (1.f + expf(-logit));

    g_mu [n*160 + t] = mu;
    g_i2s[n*160 + t] = 0.5f / sig;
    g_A1 [n*160 + t] = 0.f;
    g_A2 [n*160 + t] = 0.f;
    if (d == 0) {
        g_a[n*MM + m] = a1;
        g_K[n*MM + m] = -0.5f*sl2 - 8.f*LN2PI + logf(a1);
        g_R[n*MM + m] = 0.f;
    }
}

// ---------------- pass B/C: fused E-step + M-step statistics ----------------
__global__ __launch_bounds__(224) void k_pass(const float* __restrict__ l,
                                              const float* __restrict__ w)
{
    const int c = blockIdx.x, n = blockIdx.y;
    __shared__ float w_sh[160], mu_sh[160], i2_sh[160], K_sh[10], a_sh[10];
    __shared__ float aR[10], aA1[160], aA2[160];
    const int tid = threadIdx.x;
    if (tid < 160) {
        w_sh [tid] = w[c*160 + tid];
        mu_sh[tid] = g_mu [n*160 + tid];
        i2_sh[tid] = g_i2s[n*160 + tid];
        aA1[tid] = 0.f; aA2[tid] = 0.f;
    }
    if (tid < 10) {
        K_sh[tid] = g_K[n*10 + tid];
        a_sh[tid] = g_a[n*10 + tid];
        aR[tid] = 0.f;
    }
    __syncthreads();

    const bool act = tid < SS;
    float lv[16];
    const float* lbase = l + (size_t)(n*CC + c)*DD*SS + (act ? tid : 0);
#pragma unroll
    for (int d = 0; d < 16; d++) lv[d] = act ? lbase[d*SS] : 0.f;

    float lnap[10];
#pragma unroll
    for (int m = 0; m < 10; m++) {
        float wr[16];
#pragma unroll
        for (int k = 0; k < 16; k++) wr[k] = w_sh[m*16 + k];
        float q = 0.f;
#pragma unroll
        for (int p = 0; p < 4; p++) {
            float a0 = lv[4*p+0], a1 = lv[4*p+1], a2 = lv[4*p+2], a3 = lv[4*p+3];
#pragma unroll
            for (int r = 0; r < 4; r++) {
                float v = fmaf(a0, wr[r], fmaf(a1, wr[4+r], fmaf(a2, wr[8+r], a3*wr[12+r])));
                int idx = m*16 + p*4 + r;
                float tdiff = v - mu_sh[idx];
                q = fmaf(tdiff*tdiff, i2_sh[idx], q);
            }
        }
        lnap[m] = K_sh[m] - q;
    }

    // stable softmax over m, then r_m = p_m * a_m
    float mx = lnap[0];
#pragma unroll
    for (int m = 1; m < 10; m++) mx = fmaxf(mx, lnap[m]);
    float den = 0.f;
#pragma unroll
    for (int m = 0; m < 10; m++) { lnap[m] = expf(lnap[m] - mx); den += lnap[m]; }
    float invden = 1.f / den;
#pragma unroll
    for (int m = 0; m < 10; m++) lnap[m] = act ? lnap[m] * invden * a_sh[m] : 0.f;

    // phase 2: accumulate R, sum r*V, sum r*V^2
#pragma unroll
    for (int m = 0; m < 10; m++) {
        float wr[16];
#pragma unroll
        for (int k = 0; k < 16; k++) wr[k] = w_sh[m*16 + k];
        float rm = lnap[m];
        float rr = rm;
#pragma unroll
        for (int o = 16; o > 0; o >>= 1) rr += __shfl_xor_sync(0xffffffffu, rr, o);
        if ((tid & 31) == 0) atomicAdd(&aR[m], rr);
#pragma unroll
        for (int p = 0; p < 4; p++) {
            float a0 = lv[4*p+0], a1 = lv[4*p+1], a2 = lv[4*p+2], a3 = lv[4*p+3];
#pragma unroll
            for (int r = 0; r < 4; r++) {
                float v  = fmaf(a0, wr[r], fmaf(a1, wr[4+r], fmaf(a2, wr[8+r], a3*wr[12+r])));
                float c1 = rm * v;
                float c2 = c1 * v;
#pragma unroll
                for (int o = 16; o > 0; o >>= 1) {
                    c1 += __shfl_xor_sync(0xffffffffu, c1, o);
                    c2 += __shfl_xor_sync(0xffffffffu, c2, o);
                }
                if ((tid & 31) == 0) {
                    atomicAdd(&aA1[m*16 + p*4 + r], c1);
                    atomicAdd(&aA2[m*16 + p*4 + r], c2);
                }
            }
        }
    }
    __syncthreads();
    if (tid < 160) {
        atomicAdd(&g_A1[n*160 + tid], aA1[tid]);
        atomicAdd(&g_A2[n*160 + tid], aA2[tid]);
    }
    if (tid < 10) atomicAdd(&g_R[n*10 + tid], aR[tid]);
}

// ---------------- epilogue B: M-step finalize + new E-constants ----------------
__global__ void k_epiB(const float* __restrict__ beta_a,
                       const float* __restrict__ beta_u)
{
    const int n = blockIdx.x;
    const int t = threadIdx.x;
    const int m = t >> 4, d = t & 15;

    float R  = g_R [n*10 + m];
    float A1 = g_A1[n*160 + t];
    float A2 = g_A2[n*160 + t];
    float inv = 1.f / (R + EPSF);
    float mu  = A1 * inv;
    float sig = (A2 - 2.f*mu*A1 + mu*mu*R) * inv + EPSF;
    float sl  = logf(sig);
#pragma unroll
    for (int o = 8; o > 0; o >>= 1) sl += __shfl_xor_sync(0xffffffffu, sl, o);

    float ba = beta_a[m], bu = beta_u[m];
    float logit = LAM_ROUT * (ba - R * (16.f*bu + 0.5f*sl));
    float a = 1.f / (1.f + expf(-logit));

    g_mu [n*160 + t] = mu;
    g_i2s[n*160 + t] = 0.5f / sig;
    __syncthreads();                 // everyone has read R/A1/A2
    g_A1[n*160 + t] = 0.f;
    g_A2[n*160 + t] = 0.f;
    if (d == 0) {
        g_a[n*10 + m] = a;
        g_K[n*10 + m] = -0.5f*sl - 8.f*LN2PI + logf(a);
        g_R[n*10 + m] = 0.f;
    }
}

// ---------------- final epilogue: write a_out then mu ----------------
__global__ void k_final(const float* __restrict__ beta_a,
                        const float* __restrict__ beta_u,
                        float* __restrict__ out)
{
    const int n = blockIdx.x;
    const int t = threadIdx.x;
    const int m = t >> 4, d = t & 15;

    float R  = g_R [n*10 + m];
    float A1 = g_A1[n*160 + t];
    float A2 = g_A2[n*160 + t];
    float inv = 1.f / (R + EPSF);
    float mu  = A1 * inv;
    float sig = (A2 - 2.f*mu*A1 + mu*mu*R) * inv + EPSF;
    float sl  = logf(sig);
#pragma unroll
    for (int o = 8; o > 0; o >>= 1) sl += __shfl_xor_sync(0xffffffffu, sl, o);

    float ba = beta_a[m], bu = beta_u[m];
    float logit = LAM_ROUT * (ba - R * (16.f*bu + 0.5f*sl));
    float a = 1.f / (1.f + expf(-logit));

    out[NN*MM + n*160 + t] = mu;      // mu: (N, M, 16) after a_out block
    if (d == 0) out[n*10 + m] = a;    // a_out: (N, M)
    (void)d;
}

extern "C" void kernel_launch(void* const* d_in, const int* in_sizes, int n_in,
                              void* d_out, int out_size)
{
    const float* l      = (const float*)d_in[0];
    const float* g      = (const float*)d_in[1];
    const float* weight = (const float*)d_in[2];
    const float* beta_a = (const float*)d_in[3];
    const float* beta_u = (const float*)d_in[4];
    float* out = (float*)d_out;

    dim3 gridP(CC, NN);

    k_init <<<(NN*MM*DD + 255)/256, 256>>>();
    k_passA<<<gridP, 224>>>(l, weight);
    k_epiA <<<NN, 160>>>(g, beta_a, beta_u);
    k_pass <<<gridP, 224>>>(l, weight);     // iter 1
    k_epiB <<<NN, 160>>>(beta_a, beta_u);
    k_pass <<<gridP, 224>>>(l, weight);     // iter 2
    k_final<<<NN, 160>>>(beta_a, beta_u, out);

    (void)in_sizes; (void)n_in; (void)out_size;
}

// round 2
// speedup vs baseline: 3.8852x; 3.8852x over previous
#include <cuda_runtime.h>
#include <math.h>

#define NN 32
#define CC 32
#define MM 10
#define DD 16
#define SS 196
#define BBF 6272.0f
#define EPSF 1e-6f
#define LAM_INIT 0.001f
#define LAM_ROUT 0.001f
#define LN2PI 1.8378770664093453f

// ---- persistent scratch (no cudaMalloc allowed) ----
__device__ float g_S1[NN*MM*DD];
__device__ float g_S2[NN*MM*DD];
__device__ float g_R [NN*MM];
__device__ float g_A1[NN*MM*DD];
__device__ float g_A2[NN*MM*DD];
__device__ float g_mu2[NN*MM*DD];   // 2*mu*i2 = mu/sigma
__device__ float g_i2s[NN*MM*DD];   // 1/(2*sigma)
__device__ float g_K [NN*MM];       // -0.5*sum log(sig) - 8*LN2PI + log(a) - sum mu^2*i2
__device__ float g_a [NN*MM];

// ---- multi-value halving reductions ----
// reduce 32 values across 32 lanes; returns the single sum this lane owns.
// lane L owns value index idx5(L) = bitreverse5(L).
__device__ __forceinline__ float reduce32_to_lane(float (&y)[32], int lane)
{
#pragma unroll
    for (int j = 0; j < 16; j++) {
        bool up = lane & 1;
        float s = up ? y[j] : y[j+16];
        float k = up ? y[j+16] : y[j];
        y[j] = k + __shfl_xor_sync(0xffffffffu, s, 1);
    }
#pragma unroll
    for (int j = 0; j < 8; j++) {
        bool up = lane & 2;
        float s = up ? y[j] : y[j+8];
        float k = up ? y[j+8] : y[j];
        y[j] = k + __shfl_xor_sync(0xffffffffu, s, 2);
    }
#pragma unroll
    for (int j = 0; j < 4; j++) {
        bool up = lane & 4;
        float s = up ? y[j] : y[j+4];
        float k = up ? y[j+4] : y[j];
        y[j] = k + __shfl_xor_sync(0xffffffffu, s, 4);
    }
#pragma unroll
    for (int j = 0; j < 2; j++) {
        bool up = lane & 8;
        float s = up ? y[j] : y[j+2];
        float k = up ? y[j+2] : y[j];
        y[j] = k + __shfl_xor_sync(0xffffffffu, s, 8);
    }
    {
        bool up = lane & 16;
        float s = up ? y[0] : y[1];
        float k = up ? y[1] : y[0];
        y[0] = k + __shfl_xor_sync(0xffffffffu, s, 16);
    }
    return y[0];
}
__device__ __forceinline__ int idx5_of_lane(int lane) {
    return ((lane&1)<<4) | (((lane>>1)&1)<<3) | (((lane>>2)&1)<<2)
         | (((lane>>3)&1)<<1) | ((lane>>4)&1);
}

// reduce 16 values across 32 lanes; lane L owns index bitreverse4(L&15),
// duplicated across the two 16-lane halves.
__device__ __forceinline__ float reduce16_to_lane(float (&y)[16], int lane)
{
#pragma unroll
    for (int j = 0; j < 8; j++) {
        bool up = lane & 1;
        float s = up ? y[j] : y[j+8];
        float k = up ? y[j+8] : y[j];
        y[j] = k + __shfl_xor_sync(0xffffffffu, s, 1);
    }
#pragma unroll
    for (int j = 0; j < 4; j++) {
        bool up = lane & 2;
        float s = up ? y[j] : y[j+4];
        float k = up ? y[j+4] : y[j];
        y[j] = k + __shfl_xor_sync(0xffffffffu, s, 2);
    }
#pragma unroll
    for (int j = 0; j < 2; j++) {
        bool up = lane & 4;
        float s = up ? y[j] : y[j+2];
        float k = up ? y[j+2] : y[j];
        y[j] = k + __shfl_xor_sync(0xffffffffu, s, 4);
    }
    {
        bool up = lane & 8;
        float s = up ? y[0] : y[1];
        float k = up ? y[1] : y[0];
        y[0] = k + __shfl_xor_sync(0xffffffffu, s, 8);
    }
    y[0] += __shfl_xor_sync(0xffffffffu, y[0], 16);
    return y[0];
}
__device__ __forceinline__ int idx4_of_lane(int lane) {
    return ((lane&1)<<3) | (((lane>>1)&1)<<2) | (((lane>>2)&1)<<1) | ((lane>>3)&1);
}

__global__ void k_init()
{
    int i = blockIdx.x * blockDim.x + threadIdx.x;
    if (i < NN*MM*DD) { g_S1[i] = 0.f; g_S2[i] = 0.f; }
}

// ---------------- pass A: S1 = sum_i V, S2 = sum_i V^2 ----------------
__global__ __launch_bounds__(224) void k_passA(const float* __restrict__ l,
                                               const float* __restrict__ w)
{
    const int c = blockIdx.x, n = blockIdx.y;
    __shared__ float w_sh[160];
    __shared__ float acc1[160], acc2[160];
    const int tid = threadIdx.x;
    const int lane = tid & 31;
    if (tid < 160) { w_sh[tid] = w[c*160 + tid]; acc1[tid] = 0.f; acc2[tid] = 0.f; }
    __syncthreads();

    const bool act = tid < SS;
    float lv[16];
    const float* lbase = l + (size_t)(n*CC + c)*DD*SS + (act ? tid : 0);
#pragma unroll
    for (int d = 0; d < 16; d++) lv[d] = act ? lbase[d*SS] : 0.f;

    const int idx5 = idx5_of_lane(lane);

#pragma unroll
    for (int m = 0; m < MM; m++) {
        float wr[16];
#pragma unroll
        for (int k = 0; k < 16; k++) wr[k] = w_sh[m*16 + k];
        float y[32];
#pragma unroll
        for (int p = 0; p < 4; p++) {
            float a0 = lv[4*p+0], a1 = lv[4*p+1], a2 = lv[4*p+2], a3 = lv[4*p+3];
#pragma unroll
            for (int r = 0; r < 4; r++) {
                float v = fmaf(a0, wr[r], fmaf(a1, wr[4+r], fmaf(a2, wr[8+r], a3*wr[12+r])));
                y[p*4+r] = v;
                y[16 + p*4+r] = v*v;
            }
        }
        float val = reduce32_to_lane(y, lane);
        if (idx5 < 16) atomicAdd(&acc1[m*16 + idx5], val);
        else           atomicAdd(&acc2[m*16 + idx5 - 16], val);
    }
    __syncthreads();
    if (tid < 160) {
        atomicAdd(&g_S1[n*160 + tid], acc1[tid]);
        atomicAdd(&g_S2[n*160 + tid], acc2[tid]);
    }
}

// ---------------- epilogue A: init a, iter0 M-step, E-constants ----------------
__global__ void k_epiA(const float* __restrict__ g,
                       const float* __restrict__ beta_a,
                       const float* __restrict__ beta_u)
{
    const int n = blockIdx.x;
    const int t = threadIdx.x;           // 160 threads
    const int m = t >> 4, d = t & 15;

    float S1 = g_S1[n*160 + t], S2 = g_S2[n*160 + t];
    float gv = g[(n*MM + m)*DD + d];

    float sig0 = S2 - 2.f*gv*S1 + BBF*gv*gv + EPSF;
    float sl = logf(sig0);
#pragma unroll
    for (int o = 8; o > 0; o >>= 1) sl += __shfl_xor_sync(0xffffffffu, sl, o);

    float ba = beta_a[m], bu = beta_u[m];
    float a0 = 1.f / (1.f + expf(-(LAM_INIT * (ba - 16.f*bu - 0.5f*sl))));

    float rsum  = BBF * a0 * 0.1f;
    float coeff = (a0 * 0.1f) / (rsum + EPSF);
    float mu    = coeff * S1;
    float sig   = coeff * (S2 - 2.f*mu*S1 + BBF*mu*mu) + EPSF;
    float sl2 = logf(sig);
#pragma unroll
    for (int o = 8; o > 0; o >>= 1) sl2 += __shfl_xor_sync(0xffffffffu, sl2, o);

    float logit = LAM_ROUT * (ba - rsum * (16.f*bu + 0.5f*sl2));
    float a1 = 1.f / (1.f + expf(-logit));

    float i2  = 0.5f / sig;
    float cst = mu*mu*i2;
#pragma unroll
    for (int o = 8; o > 0; o >>= 1) cst += __shfl_xor_sync(0xffffffffu, cst, o);

    g_mu2[n*160 + t] = mu / sig;         // 2*mu*i2
    g_i2s[n*160 + t] = i2;
    g_A1 [n*160 + t] = 0.f;
    g_A2 [n*160 + t] = 0.f;
    if (d == 0) {
        g_a[n*MM + m] = a1;
        g_K[n*MM + m] = -0.5f*sl2 - 8.f*LN2PI + logf(a1) - cst;
        g_R[n*MM + m] = 0.f;
    }
}

// ---------------- pass B/C: fused E-step + M-step statistics ----------------
__global__ __launch_bounds__(224) void k_pass(const float* __restrict__ l,
                                              const float* __restrict__ w)
{
    const int c = blockIdx.x, n = blockIdx.y;
    __shared__ float w_sh[160], mu2_sh[160], i2_sh[160], K_sh[10], a_sh[10];
    __shared__ float aR[10], aA1[160], aA2[160];
    const int tid = threadIdx.x;
    const int lane = tid & 31;
    if (tid < 160) {
        w_sh [tid] = w[c*160 + tid];
        mu2_sh[tid] = g_mu2[n*160 + tid];
        i2_sh[tid]  = g_i2s[n*160 + tid];
        aA1[tid] = 0.f; aA2[tid] = 0.f;
    }
    if (tid < 10) {
        K_sh[tid] = g_K[n*10 + tid];
        a_sh[tid] = g_a[n*10 + tid];
        aR[tid] = 0.f;
    }
    __syncthreads();

    const bool act = tid < SS;
    float lv[16];
    const float* lbase = l + (size_t)(n*CC + c)*DD*SS + (act ? tid : 0);
#pragma unroll
    for (int d = 0; d < 16; d++) lv[d] = act ? lbase[d*SS] : 0.f;

    // ---- phase 1: ln a_m p_m(x_i) for all m ----
    float lnap[10];
#pragma unroll
    for (int m = 0; m < 10; m++) {
        float wr[16];
#pragma unroll
        for (int k = 0; k < 16; k++) wr[k] = w_sh[m*16 + k];
        float q = 0.f;
#pragma unroll
        for (int p = 0; p < 4; p++) {
            float a0 = lv[4*p+0], a1 = lv[4*p+1], a2 = lv[4*p+2], a3 = lv[4*p+3];
#pragma unroll
            for (int r = 0; r < 4; r++) {
                float v = fmaf(a0, wr[r], fmaf(a1, wr[4+r], fmaf(a2, wr[8+r], a3*wr[12+r])));
                int idx = m*16 + p*4 + r;
                float t1 = fmaf(v, i2_sh[idx], -mu2_sh[idx]);
                q = fmaf(v, t1, q);
            }
        }
        lnap[m] = K_sh[m] - q;
    }

    // ---- stable softmax, r_m = softmax_m * a_m ----
    float mx = lnap[0];
#pragma unroll
    for (int m = 1; m < 10; m++) mx = fmaxf(mx, lnap[m]);
    float den = 0.f;
#pragma unroll
    for (int m = 0; m < 10; m++) { lnap[m] = expf(lnap[m] - mx); den += lnap[m]; }
    float invden = 1.f / den;
#pragma unroll
    for (int m = 0; m < 10; m++) lnap[m] = act ? lnap[m] * invden * a_sh[m] : 0.f;

    // ---- phase 2: accumulate sum r*V, sum r*V^2 ----
    const int idx5 = idx5_of_lane(lane);
#pragma unroll
    for (int m = 0; m < 10; m++) {
        float wr[16];
#pragma unroll
        for (int k = 0; k < 16; k++) wr[k] = w_sh[m*16 + k];
        float rm = lnap[m];
        float y[32];
#pragma unroll
        for (int p = 0; p < 4; p++) {
            float a0 = lv[4*p+0], a1 = lv[4*p+1], a2 = lv[4*p+2], a3 = lv[4*p+3];
#pragma unroll
            for (int r = 0; r < 4; r++) {
                float v  = fmaf(a0, wr[r], fmaf(a1, wr[4+r], fmaf(a2, wr[8+r], a3*wr[12+r])));
                float c1 = rm * v;
                y[p*4+r] = c1;
                y[16 + p*4+r] = c1 * v;
            }
        }
        float val = reduce32_to_lane(y, lane);
        if (idx5 < 16) atomicAdd(&aA1[m*16 + idx5], val);
        else           atomicAdd(&aA2[m*16 + idx5 - 16], val);
    }

    // ---- R reduction: 10 values padded to 16 ----
    {
        float y[16];
#pragma unroll
        for (int m = 0; m < 10; m++) y[m] = lnap[m];
#pragma unroll
        for (int m = 10; m < 16; m++) y[m] = 0.f;
        float val = reduce16_to_lane(y, lane);
        int idx4 = idx4_of_lane(lane);
        if (lane < 16 && idx4 < 10) atomicAdd(&aR[idx4], val);
    }

    __syncthreads();
    if (tid < 160) {
        atomicAdd(&g_A1[n*160 + tid], aA1[tid]);
        atomicAdd(&g_A2[n*160 + tid], aA2[tid]);
    }
    if (tid < 10) atomicAdd(&g_R[n*10 + tid], aR[tid]);
}

// ---------------- epilogue B: M-step finalize + new E-constants ----------------
__global__ void k_epiB(const float* __restrict__ beta_a,
                       const float* __restrict__ beta_u)
{
    const int n = blockIdx.x;
    const int t = threadIdx.x;
    const int m = t >> 4, d = t & 15;

    float R  = g_R [n*10 + m];
    float A1 = g_A1[n*160 + t];
    float A2 = g_A2[n*160 + t];
    float inv = 1.f / (R + EPSF);
    float mu  = A1 * inv;
    float sig = (A2 - 2.f*mu*A1 + mu*mu*R) * inv + EPSF;
    float sl  = logf(sig);
#pragma unroll
    for (int o = 8; o > 0; o >>= 1) sl += __shfl_xor_sync(0xffffffffu, sl, o);

    float ba = beta_a[m], bu = beta_u[m];
    float logit = LAM_ROUT * (ba - R * (16.f*bu + 0.5f*sl));
    float a = 1.f / (1.f + expf(-logit));

    float i2  = 0.5f / sig;
    float cst = mu*mu*i2;
#pragma unroll
    for (int o = 8; o > 0; o >>= 1) cst += __shfl_xor_sync(0xffffffffu, cst, o);

    g_mu2[n*160 + t] = mu / sig;
    g_i2s[n*160 + t] = i2;
    g_A1 [n*160 + t] = 0.f;
    g_A2 [n*160 + t] = 0.f;
    if (d == 0) {
        g_a[n*10 + m] = a;
        g_K[n*10 + m] = -0.5f*sl - 8.f*LN2PI + logf(a) - cst;
        g_R[n*10 + m] = 0.f;
    }
}

// ---------------- final epilogue: write a_out then mu ----------------
__global__ void k_final(const float* __restrict__ beta_a,
                        const float* __restrict__ beta_u,
                        float* __restrict__ out)
{
    const int n = blockIdx.x;
    const int t = threadIdx.x;
    const int m = t >> 4, d = t & 15;

    float R  = g_R [n*10 + m];
    float A1 = g_A1[n*160 + t];
    float A2 = g_A2[n*160 + t];
    float inv = 1.f / (R + EPSF);
    float mu  = A1 * inv;
    float sig = (A2 - 2.f*mu*A1 + mu*mu*R) * inv + EPSF;
    float sl  = logf(sig);
#pragma unroll
    for (int o = 8; o > 0; o >>= 1) sl += __shfl_xor_sync(0xffffffffu, sl, o);

    float ba = beta_a[m], bu = beta_u[m];
    float logit = LAM_ROUT * (ba - R * (16.f*bu + 0.5f*sl));
    float a = 1.f / (1.f + expf(-logit));

    out[NN*MM + n*160 + t] = mu;      // mu block: (N, M, 16)
    if (d == 0) out[n*10 + m] = a;    // a_out block: (N, M)
}

extern "C" void kernel_launch(void* const* d_in, const int* in_sizes, int n_in,
                              void* d_out, int out_size)
{
    const float* l      = (const float*)d_in[0];
    const float* g      = (const float*)d_in[1];
    const float* weight = (const float*)d_in[2];
    const float* beta_a = (const float*)d_in[3];
    const float* beta_u = (const float*)d_in[4];
    float* out = (float*)d_out;

    dim3 gridP(CC, NN);

    k_init <<<(NN*MM*DD + 255)/256, 256>>>();
    k_passA<<<gridP, 224>>>(l, weight);
    k_epiA <<<NN, 160>>>(g, beta_a, beta_u);
    k_pass <<<gridP, 224>>>(l, weight);     // routing iter 1
    k_epiB <<<NN, 160>>>(beta_a, beta_u);
    k_pass <<<gridP, 224>>>(l, weight);     // routing iter 2
    k_final<<<NN, 160>>>(beta_a, beta_u, out);

    (void)in_sizes; (void)n_in; (void)out_size;
}

// round 5
// speedup vs baseline: 4.5649x; 1.1749x over previous
#include <cuda_runtime.h>
#include <math.h>

#define NN 32
#define CC 32
#define MM 10
#define SS 196
#define BBF 6272.0f
#define EPSF 1e-6f
#define LAM_INIT 0.001f
#define LAM_ROUT 0.001f
#define LN2PI 1.8378770664093453f

typedef unsigned long long u64;

// ---- persistent scratch (zero-initialized at module load; every kernel that
// consumes an accumulator resets it, so CUDA-graph replays stay correct) ----
__device__ float g_S1[NN*MM*16];
__device__ float g_S2[NN*MM*16];
__device__ float g_R [NN*MM];
__device__ float g_A1[NN*MM*16];
__device__ float g_A2[NN*MM*16];
__device__ float g_mu2n[NN*MM*16];  // -mu/sigma
__device__ float g_i2s [NN*MM*16];  // 1/(2*sigma)
__device__ float g_K [NN*MM];       // -0.5*sum log(sig) - 8*LN2PI + log(a) - sum mu^2/(2 sig)
__device__ float g_a [NN*MM];

// ---- packed f32x2 helpers ----
__device__ __forceinline__ u64 pk2(float lo, float hi) {
    u64 r; asm("mov.b64 %0, {%1,%2};" : "=l"(r) : "f"(lo), "f"(hi)); return r;
}
__device__ __forceinline__ u64 bc2(float x) { return pk2(x, x); }
__device__ __forceinline__ void upk(u64 v, float& lo, float& hi) {
    asm("mov.b64 {%0,%1}, %2;" : "=f"(lo), "=f"(hi) : "l"(v));
}
__device__ __forceinline__ u64 fma2(u64 a, u64 b, u64 c) {
    u64 d; asm("fma.rn.f32x2 %0, %1, %2, %3;" : "=l"(d) : "l"(a), "l"(b), "l"(c)); return d;
}
__device__ __forceinline__ u64 mul2(u64 a, u64 b) {
    u64 d; asm("mul.rn.f32x2 %0, %1, %2;" : "=l"(d) : "l"(a), "l"(b)); return d;
}
__device__ __forceinline__ u64 add2(u64 a, u64 b) {
    u64 d; asm("add.rn.f32x2 %0, %1, %2;" : "=l"(d) : "l"(a), "l"(b)); return d;
}

__device__ __forceinline__ int bitrev4(int x) {
    return ((x&1)<<3) | (((x>>1)&1)<<2) | (((x>>2)&1)<<1) | ((x>>3)&1);
}

// packed halving reduction: 16 u64 (= 32 scalars) summed across 32 lanes.
// Returns the single scalar this lane owns:
//   scalar index = 2*bitrev4(lane&15) + ((lane>>4)&1)
__device__ __forceinline__ float reduce32p(u64 (&y)[16], int lane)
{
#pragma unroll
    for (int j = 0; j < 8; j++) {
        bool up = lane & 1;
        u64 s = up ? y[j] : y[j+8];
        u64 k = up ? y[j+8] : y[j];
        y[j] = add2(k, __shfl_xor_sync(0xffffffffu, s, 1));
    }
#pragma unroll
    for (int j = 0; j < 4; j++) {
        bool up = lane & 2;
        u64 s = up ? y[j] : y[j+4];
        u64 k = up ? y[j+4] : y[j];
        y[j] = add2(k, __shfl_xor_sync(0xffffffffu, s, 2));
    }
#pragma unroll
    for (int j = 0; j < 2; j++) {
        bool up = lane & 4;
        u64 s = up ? y[j] : y[j+2];
        u64 k = up ? y[j+2] : y[j];
        y[j] = add2(k, __shfl_xor_sync(0xffffffffu, s, 4));
    }
    {
        bool up = lane & 8;
        u64 s = up ? y[0] : y[1];
        u64 k = up ? y[1] : y[0];
        y[0] = add2(k, __shfl_xor_sync(0xffffffffu, s, 8));
    }
    float lo, hi; upk(y[0], lo, hi);
    bool up = lane & 16;
    float s = up ? lo : hi;
    float k = up ? hi : lo;
    return k + __shfl_xor_sync(0xffffffffu, s, 16);
}

// 16 scalars across 32 lanes (for R, padded); lane owns bitrev4(lane&15), halves duplicated.
__device__ __forceinline__ float reduce16_to_lane(float (&y)[16], int lane)
{
#pragma unroll
    for (int j = 0; j < 8; j++) {
        bool up = lane & 1;
        float s = up ? y[j] : y[j+8];
        float k = up ? y[j+8] : y[j];
        y[j] = k + __shfl_xor_sync(0xffffffffu, s, 1);
    }
#pragma unroll
    for (int j = 0; j < 4; j++) {
        bool up = lane & 2;
        float s = up ? y[j] : y[j+4];
        float k = up ? y[j+4] : y[j];
        y[j] = k + __shfl_xor_sync(0xffffffffu, s, 2);
    }
#pragma unroll
    for (int j = 0; j < 2; j++) {
        bool up = lane & 4;
        float s = up ? y[j] : y[j+2];
        float k = up ? y[j+2] : y[j];
        y[j] = k + __shfl_xor_sync(0xffffffffu, s, 4);
    }
    {
        bool up = lane & 8;
        float s = up ? y[0] : y[1];
        float k = up ? y[1] : y[0];
        y[0] = k + __shfl_xor_sync(0xffffffffu, s, 8);
    }
    y[0] += __shfl_xor_sync(0xffffffffu, y[0], 16);
    return y[0];
}

// ---------------- pass A: S1 = sum_i V, S2 = sum_i V^2 ----------------
__global__ __launch_bounds__(224) void k_passA(const float* __restrict__ l,
                                               const float* __restrict__ w)
{
    const int c = blockIdx.x, n = blockIdx.y;
    __shared__ alignas(16) float w_sh[160];
    __shared__ float acc1[160], acc2[160];
    const int tid = threadIdx.x, lane = tid & 31;
    if (tid < 160) { w_sh[tid] = w[c*160 + tid]; acc1[tid] = 0.f; acc2[tid] = 0.f; }
    __syncthreads();

    const bool act = tid < SS;
    const float* lbase = l + (size_t)(n*CC + c)*16*SS + (act ? tid : 0);
    u64 lvp[16];
#pragma unroll
    for (int d = 0; d < 16; d++) lvp[d] = bc2(act ? lbase[d*SS] : 0.f);

    const int slot = bitrev4(lane & 15);
    const int e    = (lane >> 4) & 1;
    const int comp = 2*(slot & 7) + e;
    float* accp = (slot < 8) ? (acc1 + comp) : (acc2 + comp);

#pragma unroll
    for (int m = 0; m < MM; m++) {
        const ulonglong2* wv = (const ulonglong2*)&w_sh[m*16];
        u64 w01[4], w23[4];
#pragma unroll
        for (int q = 0; q < 4; q++) { ulonglong2 t = wv[q]; w01[q] = t.x; w23[q] = t.y; }
        u64 y[16];
#pragma unroll
        for (int p = 0; p < 4; p++) {
            u64 a0 = lvp[4*p], a1 = lvp[4*p+1], a2 = lvp[4*p+2], a3 = lvp[4*p+3];
#pragma unroll
            for (int rp = 0; rp < 2; rp++) {
                const u64* wc = rp ? w23 : w01;
                u64 v = fma2(a0, wc[0], fma2(a1, wc[1], fma2(a2, wc[2], mul2(a3, wc[3]))));
                y[p*2 + rp]     = v;
                y[8 + p*2 + rp] = mul2(v, v);
            }
        }
        float own = reduce32p(y, lane);
        atomicAdd(accp + m*16, own);
    }
    __syncthreads();
    if (tid < 160) {
        atomicAdd(&g_S1[n*160 + tid], acc1[tid]);
        atomicAdd(&g_S2[n*160 + tid], acc2[tid]);
    }
}

// ---------------- epilogue A: init a, iter0 M-step, E-constants ----------------
__global__ void k_epiA(const float* __restrict__ g,
                       const float* __restrict__ beta_a,
                       const float* __restrict__ beta_u)
{
    const int n = blockIdx.x;
    const int t = threadIdx.x;           // 160 threads
    const int m = t >> 4, d = t & 15;

    float S1 = g_S1[n*160 + t], S2 = g_S2[n*160 + t];
    g_S1[n*160 + t] = 0.f;               // self-clean for next replay
    g_S2[n*160 + t] = 0.f;
    float gv = g[(n*MM + m)*16 + d];

    float sig0 = S2 - 2.f*gv*S1 + BBF*gv*gv + EPSF;
    float sl = logf(sig0);
#pragma unroll
    for (int o = 8; o > 0; o >>= 1) sl += __shfl_xor_sync(0xffffffffu, sl, o);

    float ba = beta_a[m], bu = beta_u[m];
    float a0 = 1.f / (1.f + expf(-(LAM_INIT * (ba - 16.f*bu - 0.5f*sl))));

    float rsum  = BBF * a0 * 0.1f;
    float coeff = (a0 * 0.1f) / (rsum + EPSF);
    float mu    = coeff * S1;
    float sig   = coeff * (S2 - 2.f*mu*S1 + BBF*mu*mu) + EPSF;
    float sl2 = logf(sig);
#pragma unroll
    for (int o = 8; o > 0; o >>= 1) sl2 += __shfl_xor_sync(0xffffffffu, sl2, o);

    float logit = LAM_ROUT * (ba - rsum * (16.f*bu + 0.5f*sl2));
    float a1 = 1.f / (1.f + expf(-logit));

    float i2  = 0.5f / sig;
    float cst = mu*mu*i2;
#pragma unroll
    for (int o = 8; o > 0; o >>= 1) cst += __shfl_xor_sync(0xffffffffu, cst, o);

    g_mu2n[n*160 + t] = -(mu / sig);
    g_i2s [n*160 + t] = i2;
    g_A1  [n*160 + t] = 0.f;
    g_A2  [n*160 + t] = 0.f;
    if (d == 0) {
        g_a[n*MM + m] = a1;
        g_K[n*MM + m] = -0.5f*sl2 - 8.f*LN2PI + logf(a1) - cst;
        g_R[n*MM + m] = 0.f;
    }
}

// ---------------- pass B/C: fused E-step + M-step statistics ----------------
__global__ __launch_bounds__(224) void k_pass(const float* __restrict__ l,
                                              const float* __restrict__ w)
{
    const int c = blockIdx.x, n = blockIdx.y;
    __shared__ alignas(16) float w_sh[160];
    __shared__ alignas(16) float i2_sh[160];
    __shared__ alignas(16) float mu_sh[160];
    __shared__ float K_sh[10], a_sh[10], aR[10];
    __shared__ float aA1[160], aA2[160];
    const int tid = threadIdx.x, lane = tid & 31;
    if (tid < 160) {
        w_sh [tid] = w[c*160 + tid];
        i2_sh[tid] = g_i2s [n*160 + tid];
        mu_sh[tid] = g_mu2n[n*160 + tid];
        aA1[tid] = 0.f; aA2[tid] = 0.f;
    }
    if (tid < 10) {
        K_sh[tid] = g_K[n*10 + tid];
        a_sh[tid] = g_a[n*10 + tid];
        aR[tid] = 0.f;
    }
    __syncthreads();

    const bool act = tid < SS;
    const float* lbase = l + (size_t)(n*CC + c)*16*SS + (act ? tid : 0);
    u64 lvp[16];
#pragma unroll
    for (int d = 0; d < 16; d++) lvp[d] = bc2(act ? lbase[d*SS] : 0.f);

    // ---- phase 1: ln a_m p_m(x_i) ----
    float lnap[10];
#pragma unroll
    for (int m = 0; m < 10; m++) {
        const ulonglong2* wv  = (const ulonglong2*)&w_sh [m*16];
        const ulonglong2* i2v = (const ulonglong2*)&i2_sh[m*16];
        const ulonglong2* muv = (const ulonglong2*)&mu_sh[m*16];
        u64 w01[4], w23[4];
#pragma unroll
        for (int q = 0; q < 4; q++) { ulonglong2 t = wv[q]; w01[q] = t.x; w23[q] = t.y; }
        u64 qacc = 0ull;
#pragma unroll
        for (int p = 0; p < 4; p++) {
            u64 a0 = lvp[4*p], a1 = lvp[4*p+1], a2 = lvp[4*p+2], a3 = lvp[4*p+3];
            ulonglong2 i2q = i2v[p], muq = muv[p];
#pragma unroll
            for (int rp = 0; rp < 2; rp++) {
                const u64* wc = rp ? w23 : w01;
                u64 v = fma2(a0, wc[0], fma2(a1, wc[1], fma2(a2, wc[2], mul2(a3, wc[3]))));
                u64 t1 = fma2(v, rp ? i2q.y : i2q.x, rp ? muq.y : muq.x);
                qacc = fma2(v, t1, qacc);
            }
        }
        float ql, qh; upk(qacc, ql, qh);
        lnap[m] = K_sh[m] - (ql + qh);
    }

    // ---- stable softmax, r_m = softmax_m * a_m ----
    float mx = lnap[0];
#pragma unroll
    for (int m = 1; m < 10; m++) mx = fmaxf(mx, lnap[m]);
    float den = 0.f;
#pragma unroll
    for (int m = 0; m < 10; m++) { lnap[m] = __expf(lnap[m] - mx); den += lnap[m]; }
    float sc = 1.f / den;
#pragma unroll
    for (int m = 0; m < 10; m++) lnap[m] = act ? lnap[m] * sc * a_sh[m] : 0.f;

    // ---- phase 2: accumulate sum r*V, sum r*V^2 ----
    const int slot = bitrev4(lane & 15);
    const int e    = (lane >> 4) & 1;
    const int comp = 2*(slot & 7) + e;
    float* accp = (slot < 8) ? (aA1 + comp) : (aA2 + comp);

#pragma unroll
    for (int m = 0; m < 10; m++) {
        const ulonglong2* wv = (const ulonglong2*)&w_sh[m*16];
        u64 w01[4], w23[4];
#pragma unroll
        for (int q = 0; q < 4; q++) { ulonglong2 t = wv[q]; w01[q] = t.x; w23[q] = t.y; }
        u64 rmp = bc2(lnap[m]);
        u64 y[16];
#pragma unroll
        for (int p = 0; p < 4; p++) {
            u64 a0 = lvp[4*p], a1 = lvp[4*p+1], a2 = lvp[4*p+2], a3 = lvp[4*p+3];
#pragma unroll
            for (int rp = 0; rp < 2; rp++) {
                const u64* wc = rp ? w23 : w01;
                u64 v  = fma2(a0, wc[0], fma2(a1, wc[1], fma2(a2, wc[2], mul2(a3, wc[3]))));
                u64 c1 = mul2(rmp, v);
                y[p*2 + rp]     = c1;
                y[8 + p*2 + rp] = mul2(c1, v);
            }
        }
        float own = reduce32p(y, lane);
        atomicAdd(accp + m*16, own);
    }

    // ---- R reduction (10 values padded to 16) ----
    {
        float y[16];
#pragma unroll
        for (int m = 0; m < 10; m++) y[m] = lnap[m];
#pragma unroll
        for (int m = 10; m < 16; m++) y[m] = 0.f;
        float val = reduce16_to_lane(y, lane);
        int idx4 = bitrev4(lane & 15);
        if (lane < 16 && idx4 < 10) atomicAdd(&aR[idx4], val);
    }

    __syncthreads();
    if (tid < 160) {
        atomicAdd(&g_A1[n*160 + tid], aA1[tid]);
        atomicAdd(&g_A2[n*160 + tid], aA2[tid]);
    }
    if (tid < 10) atomicAdd(&g_R[n*10 + tid], aR[tid]);
}

// ---------------- epilogue B: M-step finalize + new E-constants ----------------
__global__ void k_epiB(const float* __restrict__ beta_a,
                       const float* __restrict__ beta_u)
{
    const int n = blockIdx.x;
    const int t = threadIdx.x;
    const int m = t >> 4, d = t & 15;

    float R  = g_R [n*10 + m];
    float A1 = g_A1[n*160 + t];
    float A2 = g_A2[n*160 + t];
    float inv = 1.f / (R + EPSF);
    float mu  = A1 * inv;
    float sig = (A2 - 2.f*mu*A1 + mu*mu*R) * inv + EPSF;
    float sl  = logf(sig);
#pragma unroll
    for (int o = 8; o > 0; o >>= 1) sl += __shfl_xor_sync(0xffffffffu, sl, o);

    float ba = beta_a[m], bu = beta_u[m];
    float logit = LAM_ROUT * (ba - R * (16.f*bu + 0.5f*sl));
    float a = 1.f / (1.f + expf(-logit));

    float i2  = 0.5f / sig;
    float cst = mu*mu*i2;
#pragma unroll
    for (int o = 8; o > 0; o >>= 1) cst += __shfl_xor_sync(0xffffffffu, cst, o);

    g_mu2n[n*160 + t] = -(mu / sig);
    g_i2s [n*160 + t] = i2;
    g_A1  [n*160 + t] = 0.f;
    g_A2  [n*160 + t] = 0.f;
    if (d == 0) {
        g_a[n*10 + m] = a;
        g_K[n*10 + m] = -0.5f*sl - 8.f*LN2PI + logf(a) - cst;
        g_R[n*10 + m] = 0.f;
    }
}

// ---------------- final epilogue: write a_out then mu ----------------
__global__ void k_final(const float* __restrict__ beta_a,
                        const float* __restrict__ beta_u,
                        float* __restrict__ out)
{
    const int n = blockIdx.x;
    const int t = threadIdx.x;
    const int m = t >> 4, d = t & 15;

    float R  = g_R [n*10 + m];
    float A1 = g_A1[n*160 + t];
    float A2 = g_A2[n*160 + t];
    g_A1[n*160 + t] = 0.f;               // self-clean for next replay
    g_A2[n*160 + t] = 0.f;
    float inv = 1.f / (R + EPSF);
    float mu  = A1 * inv;
    float sig = (A2 - 2.f*mu*A1 + mu*mu*R) * inv + EPSF;
    float sl  = logf(sig);
#pragma unroll
    for (int o = 8; o > 0; o >>= 1) sl += __shfl_xor_sync(0xffffffffu, sl, o);

    float ba = beta_a[m], bu = beta_u[m];
    float logit = LAM_ROUT * (ba - R * (16.f*bu + 0.5f*sl));
    float a = 1.f / (1.f + expf(-logit));

    out[NN*MM + n*160 + t] = mu;      // mu block: (N, M, 16)
    if (d == 0) {
        out[n*10 + m] = a;            // a_out block: (N, M)
        g_R[n*10 + m] = 0.f;          // self-clean
    }
}

extern "C" void kernel_launch(void* const* d_in, const int* in_sizes, int n_in,
                              void* d_out, int out_size)
{
    const float* l      = (const float*)d_in[0];
    const float* g      = (const float*)d_in[1];
    const float* weight = (const float*)d_in[2];
    const float* beta_a = (const float*)d_in[3];
    const float* beta_u = (const float*)d_in[4];
    float* out = (float*)d_out;

    dim3 gridP(CC, NN);

    k_passA<<<gridP, 224>>>(l, weight);
    k_epiA <<<NN, 160>>>(g, beta_a, beta_u);
    k_pass <<<gridP, 224>>>(l, weight);     // routing iter 1
    k_epiB <<<NN, 160>>>(beta_a, beta_u);
    k_pass <<<gridP, 224>>>(l, weight);     // routing iter 2
    k_final<<<NN, 160>>>(beta_a, beta_u, out);

    (void)in_sizes; (void)n_in; (void)out_size;
}

// round 6
// speedup vs baseline: 4.6325x; 1.0148x over previous
#include <cuda_runtime.h>
#include <math.h>
#include <stdint.h>

#define NN 32
#define CC 32
#define MM 10
#define SSZ 196
#define CPB 8                 // channels per CTA
#define ITEMS (CPB*SSZ)       // 1568 items per CTA
#define THREADS 448
#define BBF 6272.0f
#define EPSF 1e-6f
#define LAM_INIT 0.001f
#define LAM_ROUT 0.001f
#define LN2PI 1.8378770664093453f

typedef unsigned long long u64;

// ---- packed f32x2 helpers ----
__device__ __forceinline__ u64 pk2(float lo, float hi) {
    u64 r; asm("mov.b64 %0, {%1,%2};" : "=l"(r) : "f"(lo), "f"(hi)); return r;
}
__device__ __forceinline__ u64 bc2(float x) { return pk2(x, x); }
__device__ __forceinline__ void upk(u64 v, float& lo, float& hi) {
    asm("mov.b64 {%0,%1}, %2;" : "=f"(lo), "=f"(hi) : "l"(v));
}
__device__ __forceinline__ u64 fma2(u64 a, u64 b, u64 c) {
    u64 d; asm("fma.rn.f32x2 %0, %1, %2, %3;" : "=l"(d) : "l"(a), "l"(b), "l"(c)); return d;
}
__device__ __forceinline__ u64 mul2(u64 a, u64 b) {
    u64 d; asm("mul.rn.f32x2 %0, %1, %2;" : "=l"(d) : "l"(a), "l"(b)); return d;
}
__device__ __forceinline__ u64 add2(u64 a, u64 b) {
    u64 d; asm("add.rn.f32x2 %0, %1, %2;" : "=l"(d) : "l"(a), "l"(b)); return d;
}

__device__ __forceinline__ int bitrev4(int x) {
    return ((x&1)<<3) | (((x>>1)&1)<<2) | (((x>>2)&1)<<1) | ((x>>3)&1);
}

// ---- cluster helpers ----
__device__ __forceinline__ void cluster_sync_() {
    asm volatile("barrier.cluster.arrive.aligned;" ::: "memory");
    asm volatile("barrier.cluster.wait.aligned;"   ::: "memory");
}
__device__ __forceinline__ uint32_t smem_u32(const void* p) {
    uint32_t a;
    asm("{ .reg .u64 t; cvta.to.shared.u64 t, %1; cvt.u32.u64 %0, t; }" : "=r"(a) : "l"(p));
    return a;
}
__device__ __forceinline__ float cluster_ld_f32(uint32_t laddr, uint32_t rank) {
    uint32_t ra; float v;
    asm("mapa.shared::cluster.u32 %0, %1, %2;" : "=r"(ra) : "r"(laddr), "r"(rank));
    asm volatile("ld.shared::cluster.f32 %0, [%1];" : "=f"(v) : "r"(ra) : "memory");
    return v;
}

// packed halving reduction: 16 u64 (= 32 scalars) across 32 lanes.
// Lane owns scalar index 2*bitrev4(lane&15) + ((lane>>4)&1).
__device__ __forceinline__ float reduce32p(u64 (&y)[16], int lane)
{
#pragma unroll
    for (int j = 0; j < 8; j++) {
        bool up = lane & 1;
        u64 s = up ? y[j] : y[j+8];
        u64 k = up ? y[j+8] : y[j];
        y[j] = add2(k, __shfl_xor_sync(0xffffffffu, s, 1));
    }
#pragma unroll
    for (int j = 0; j < 4; j++) {
        bool up = lane & 2;
        u64 s = up ? y[j] : y[j+4];
        u64 k = up ? y[j+4] : y[j];
        y[j] = add2(k, __shfl_xor_sync(0xffffffffu, s, 2));
    }
#pragma unroll
    for (int j = 0; j < 2; j++) {
        bool up = lane & 4;
        u64 s = up ? y[j] : y[j+2];
        u64 k = up ? y[j+2] : y[j];
        y[j] = add2(k, __shfl_xor_sync(0xffffffffu, s, 4));
    }
    {
        bool up = lane & 8;
        u64 s = up ? y[0] : y[1];
        u64 k = up ? y[1] : y[0];
        y[0] = add2(k, __shfl_xor_sync(0xffffffffu, s, 8));
    }
    float lo, hi; upk(y[0], lo, hi);
    bool up = lane & 16;
    float s = up ? lo : hi;
    float k = up ? hi : lo;
    return k + __shfl_xor_sync(0xffffffffu, s, 16);
}

// 16 scalars across 32 lanes; lane owns bitrev4(lane&15), halves duplicated.
__device__ __forceinline__ float reduce16_to_lane(float (&y)[16], int lane)
{
#pragma unroll
    for (int j = 0; j < 8; j++) {
        bool up = lane & 1;
        float s = up ? y[j] : y[j+8];
        float k = up ? y[j+8] : y[j];
        y[j] = k + __shfl_xor_sync(0xffffffffu, s, 1);
    }
#pragma unroll
    for (int j = 0; j < 4; j++) {
        bool up = lane & 2;
        float s = up ? y[j] : y[j+4];
        float k = up ? y[j+4] : y[j];
        y[j] = k + __shfl_xor_sync(0xffffffffu, s, 2);
    }
#pragma unroll
    for (int j = 0; j < 2; j++) {
        bool up = lane & 4;
        float s = up ? y[j] : y[j+2];
        float k = up ? y[j+2] : y[j];
        y[j] = k + __shfl_xor_sync(0xffffffffu, s, 4);
    }
    {
        bool up = lane & 8;
        float s = up ? y[0] : y[1];
        float k = up ? y[1] : y[0];
        y[0] = k + __shfl_xor_sync(0xffffffffu, s, 8);
    }
    y[0] += __shfl_xor_sync(0xffffffffu, y[0], 16);
    return y[0];
}

// ======================= the single fused kernel =======================
__global__ __cluster_dims__(4,1,1) __launch_bounds__(THREADS,1)
void k_mega(const float* __restrict__ l, const float* __restrict__ g,
            const float* __restrict__ w, const float* __restrict__ beta_a,
            const float* __restrict__ beta_u, float* __restrict__ out)
{
    __shared__ alignas(16) float w_sh[CPB*160];
    __shared__ alignas(16) float i2_sh[160];   // 1/(2*sigma)
    __shared__ alignas(16) float mu_sh[160];   // -mu/sigma
    __shared__ float K_sh[10], a_sh[10];
    __shared__ float acc1[160], acc2[160], accR[16];

    const int tid = threadIdx.x, lane = tid & 31;
    const int crank = blockIdx.x & 3;          // rank within cluster (1D, size 4)
    const int n     = blockIdx.x >> 2;

    for (int i = tid; i < CPB*160; i += THREADS)
        w_sh[i] = w[(crank*CPB)*160 + i];
    if (tid < 160) { acc1[tid] = 0.f; acc2[tid] = 0.f; }
    if (tid < 16)  accR[tid] = 0.f;
    __syncthreads();

    const int slot = bitrev4(lane & 15);
    const int e    = (lane >> 4) & 1;
    const int comp = 2*(slot & 7) + e;
    float* accp = (slot < 8) ? (acc1 + comp) : (acc2 + comp);

    const uint32_t a1addr = smem_u32(&acc1[tid < 160 ? tid : 0]);
    const uint32_t a2addr = smem_u32(&acc2[tid < 160 ? tid : 0]);
    const uint32_t aRaddr = smem_u32(&accR[tid < 16  ? tid : 0]);

    const int em = (tid < 160) ? (tid >> 4) : 0;   // m index for epilogue threads
    const int ed = tid & 15;
    const float ba = beta_a[em], bu = beta_u[em];

    // ================= PASS A: S1 = sum V, S2 = sum V^2 =================
    for (int item = tid; item < ITEMS; item += THREADS) {
        const int cl = item / SSZ, s = item - cl*SSZ;
        const float* lbase = l + ((size_t)(n*CC + crank*CPB + cl)*16)*SSZ + s;
        u64 lvp[16];
#pragma unroll
        for (int d = 0; d < 16; d++) lvp[d] = bc2(lbase[d*SSZ]);

#pragma unroll
        for (int m = 0; m < MM; m++) {
            const ulonglong2* wv = (const ulonglong2*)&w_sh[cl*160 + m*16];
            u64 w01[4], w23[4];
#pragma unroll
            for (int q = 0; q < 4; q++) { ulonglong2 t = wv[q]; w01[q] = t.x; w23[q] = t.y; }
            u64 y[16];
#pragma unroll
            for (int p = 0; p < 4; p++) {
                u64 a0 = lvp[4*p], a1 = lvp[4*p+1], a2 = lvp[4*p+2], a3 = lvp[4*p+3];
#pragma unroll
                for (int rp = 0; rp < 2; rp++) {
                    const u64* wc = rp ? w23 : w01;
                    u64 v = fma2(a0, wc[0], fma2(a1, wc[1], fma2(a2, wc[2], mul2(a3, wc[3]))));
                    y[p*2 + rp]     = v;
                    y[8 + p*2 + rp] = mul2(v, v);
                }
            }
            atomicAdd(accp + m*16, reduce32p(y, lane));
        }
    }
    __syncthreads();
    cluster_sync_();

    // ----- combine S1/S2 across the 4 CTAs (deterministic rank order) -----
    float S1 = 0.f, S2 = 0.f;
    if (tid < 160) {
#pragma unroll
        for (uint32_t rk = 0; rk < 4; rk++) {
            S1 += cluster_ld_f32(a1addr, rk);
            S2 += cluster_ld_f32(a2addr, rk);
        }
    }
    cluster_sync_();                     // all CTAs finished reading peers
    if (tid < 160) { acc1[tid] = 0.f; acc2[tid] = 0.f; }

    // ----- epilogue A (init a, iter0 M-step, E-constants) -----
    if (tid < 160) {
        float gv = g[(n*MM + em)*16 + ed];
        float sig0 = S2 - 2.f*gv*S1 + BBF*gv*gv + EPSF;
        float sl = logf(sig0);
#pragma unroll
        for (int o = 8; o > 0; o >>= 1) sl += __shfl_xor_sync(0xffffffffu, sl, o);

        float a0 = 1.f / (1.f + expf(-(LAM_INIT * (ba - 16.f*bu - 0.5f*sl))));
        float rsum  = BBF * a0 * 0.1f;
        float coeff = (a0 * 0.1f) / (rsum + EPSF);
        float mu    = coeff * S1;
        float sig   = coeff * (S2 - 2.f*mu*S1 + BBF*mu*mu) + EPSF;
        float sl2 = logf(sig);
#pragma unroll
        for (int o = 8; o > 0; o >>= 1) sl2 += __shfl_xor_sync(0xffffffffu, sl2, o);

        float logit = LAM_ROUT * (ba - rsum * (16.f*bu + 0.5f*sl2));
        float a1 = 1.f / (1.f + expf(-logit));

        float i2  = 0.5f / sig;
        float cst = mu*mu*i2;
#pragma unroll
        for (int o = 8; o > 0; o >>= 1) cst += __shfl_xor_sync(0xffffffffu, cst, o);

        mu_sh[tid] = -(mu / sig);
        i2_sh[tid] = i2;
        if (ed == 0) {
            a_sh[em] = a1;
            K_sh[em] = -0.5f*sl2 - 8.f*LN2PI + logf(a1) - cst;
        }
    }
    __syncthreads();

    // ================= routing iterations 1 and 2 =================
    for (int it = 0; it < 2; it++) {
        for (int item = tid; item < ITEMS; item += THREADS) {
            const int cl = item / SSZ, s = item - cl*SSZ;
            const float* lbase = l + ((size_t)(n*CC + crank*CPB + cl)*16)*SSZ + s;
            u64 lvp[16];
#pragma unroll
            for (int d = 0; d < 16; d++) lvp[d] = bc2(lbase[d*SSZ]);

            // ---- E-step: ln a_m p_m ----
            float lnap[10];
#pragma unroll
            for (int m = 0; m < MM; m++) {
                const ulonglong2* wv  = (const ulonglong2*)&w_sh[cl*160 + m*16];
                const ulonglong2* i2v = (const ulonglong2*)&i2_sh[m*16];
                const ulonglong2* muv = (const ulonglong2*)&mu_sh[m*16];
                u64 w01[4], w23[4];
#pragma unroll
                for (int q = 0; q < 4; q++) { ulonglong2 t = wv[q]; w01[q] = t.x; w23[q] = t.y; }
                u64 qacc = 0ull;
#pragma unroll
                for (int p = 0; p < 4; p++) {
                    u64 a0 = lvp[4*p], a1 = lvp[4*p+1], a2 = lvp[4*p+2], a3 = lvp[4*p+3];
                    ulonglong2 i2q = i2v[p], muq = muv[p];
#pragma unroll
                    for (int rp = 0; rp < 2; rp++) {
                        const u64* wc = rp ? w23 : w01;
                        u64 v  = fma2(a0, wc[0], fma2(a1, wc[1], fma2(a2, wc[2], mul2(a3, wc[3]))));
                        u64 t1 = fma2(v, rp ? i2q.y : i2q.x, rp ? muq.y : muq.x);
                        qacc = fma2(v, t1, qacc);
                    }
                }
                float ql, qh; upk(qacc, ql, qh);
                lnap[m] = K_sh[m] - (ql + qh);
            }

            // stable softmax * a
            float mx = lnap[0];
#pragma unroll
            for (int m = 1; m < MM; m++) mx = fmaxf(mx, lnap[m]);
            float den = 0.f;
#pragma unroll
            for (int m = 0; m < MM; m++) { lnap[m] = __expf(lnap[m] - mx); den += lnap[m]; }
            float sc = 1.f / den;
#pragma unroll
            for (int m = 0; m < MM; m++) lnap[m] = lnap[m] * sc * a_sh[m];

            // ---- M-step statistics ----
#pragma unroll
            for (int m = 0; m < MM; m++) {
                const ulonglong2* wv = (const ulonglong2*)&w_sh[cl*160 + m*16];
                u64 w01[4], w23[4];
#pragma unroll
                for (int q = 0; q < 4; q++) { ulonglong2 t = wv[q]; w01[q] = t.x; w23[q] = t.y; }
                u64 rmp = bc2(lnap[m]);
                u64 y[16];
#pragma unroll
                for (int p = 0; p < 4; p++) {
                    u64 a0 = lvp[4*p], a1 = lvp[4*p+1], a2 = lvp[4*p+2], a3 = lvp[4*p+3];
#pragma unroll
                    for (int rp = 0; rp < 2; rp++) {
                        const u64* wc = rp ? w23 : w01;
                        u64 v  = fma2(a0, wc[0], fma2(a1, wc[1], fma2(a2, wc[2], mul2(a3, wc[3]))));
                        u64 c1 = mul2(rmp, v);
                        y[p*2 + rp]     = c1;
                        y[8 + p*2 + rp] = mul2(c1, v);
                    }
                }
                atomicAdd(accp + m*16, reduce32p(y, lane));
            }
            // R sums
            {
                float y[16];
#pragma unroll
                for (int m = 0; m < MM; m++) y[m] = lnap[m];
#pragma unroll
                for (int m = MM; m < 16; m++) y[m] = 0.f;
                float val = reduce16_to_lane(y, lane);
                int idx4 = bitrev4(lane & 15);
                if (lane < 16 && idx4 < MM) atomicAdd(&accR[idx4], val);
            }
        }
        __syncthreads();
        cluster_sync_();

        // combine A1/A2/R across CTAs
        float A1 = 0.f, A2 = 0.f, R = 0.f;
        if (tid < 160) {
#pragma unroll
            for (uint32_t rk = 0; rk < 4; rk++) {
                A1 += cluster_ld_f32(a1addr, rk);
                A2 += cluster_ld_f32(a2addr, rk);
            }
        }
        if (tid < 16) {
#pragma unroll
            for (uint32_t rk = 0; rk < 4; rk++) R += cluster_ld_f32(aRaddr, rk);
        }
        cluster_sync_();
        if (tid < 160) { acc1[tid] = 0.f; acc2[tid] = 0.f; }
        if (tid < 16)  accR[tid] = 0.f;

        if (tid < 160) {
            float Rm = __shfl_sync(0xffffffffu, R, (tid & ~15) & 31, 32);
            // lane holding R for this m: thread tid has m = tid>>4; R lives on tid%32 == m? No:
            // accR[idx] combined by threads tid<16 → broadcast via shared is simpler:
            ;
        }
        // broadcast R via shared (small, safe)
        __shared__ float Rtot[10];
        if (tid < 10) Rtot[tid] = R;
        __syncthreads();

        if (tid < 160) {
            float Rm  = Rtot[em];
            float inv = 1.f / (Rm + EPSF);
            float mu  = A1 * inv;
            float sig = (A2 - 2.f*mu*A1 + mu*mu*Rm) * inv + EPSF;
            float sl  = logf(sig);
#pragma unroll
            for (int o = 8; o > 0; o >>= 1) sl += __shfl_xor_sync(0xffffffffu, sl, o);

            float logit = LAM_ROUT * (ba - Rm * (16.f*bu + 0.5f*sl));
            float a = 1.f / (1.f + expf(-logit));

            if (it == 0) {
                float i2  = 0.5f / sig;
                float cst = mu*mu*i2;
#pragma unroll
                for (int o = 8; o > 0; o >>= 1) cst += __shfl_xor_sync(0xffffffffu, cst, o);
                mu_sh[tid] = -(mu / sig);
                i2_sh[tid] = i2;
                if (ed == 0) {
                    a_sh[em] = a;
                    K_sh[em] = -0.5f*sl - 8.f*LN2PI + logf(a) - cst;
                }
            } else if (crank == 0) {
                out[NN*MM + n*160 + tid] = mu;          // mu block (N, M, 16)
                if (ed == 0) out[n*MM + em] = a;        // a_out block (N, M)
            }
        }
        __syncthreads();
    }
}

extern "C" void kernel_launch(void* const* d_in, const int* in_sizes, int n_in,
                              void* d_out, int out_size)
{
    const float* l      = (const float*)d_in[0];
    const float* g      = (const float*)d_in[1];
    const float* weight = (const float*)d_in[2];
    const float* beta_a = (const float*)d_in[3];
    const float* beta_u = (const float*)d_in[4];
    float* out = (float*)d_out;

    k_mega<<<NN*4, THREADS>>>(l, g, weight, beta_a, beta_u, out);

    (void)in_sizes; (void)n_in; (void)out_size;
}

// round 7
// speedup vs baseline: 4.8798x; 1.0534x over previous
#include <cuda_runtime.h>
#include <math.h>
#include <stdint.h>

#define NN 32
#define CC 32
#define MM 10
#define SSZ 196
#define CPB 8                 // channels per CTA
#define ITEMS (CPB*SSZ)       // 1568 items per CTA
#define THREADS 448
#define BBF 6272.0f
#define EPSF 1e-6f
#define LAM_INIT 0.001f
#define LAM_ROUT 0.001f
#define LN2PI 1.8378770664093453f

typedef unsigned long long u64;

// ---- packed f32x2 helpers ----
__device__ __forceinline__ u64 pk2(float lo, float hi) {
    u64 r; asm("mov.b64 %0, {%1,%2};" : "=l"(r) : "f"(lo), "f"(hi)); return r;
}
__device__ __forceinline__ u64 bc2(float x) { return pk2(x, x); }
__device__ __forceinline__ void upk(u64 v, float& lo, float& hi) {
    asm("mov.b64 {%0,%1}, %2;" : "=f"(lo), "=f"(hi) : "l"(v));
}
__device__ __forceinline__ u64 fma2(u64 a, u64 b, u64 c) {
    u64 d; asm("fma.rn.f32x2 %0, %1, %2, %3;" : "=l"(d) : "l"(a), "l"(b), "l"(c)); return d;
}
__device__ __forceinline__ u64 mul2(u64 a, u64 b) {
    u64 d; asm("mul.rn.f32x2 %0, %1, %2;" : "=l"(d) : "l"(a), "l"(b)); return d;
}
__device__ __forceinline__ u64 add2(u64 a, u64 b) {
    u64 d; asm("add.rn.f32x2 %0, %1, %2;" : "=l"(d) : "l"(a), "l"(b)); return d;
}
__device__ __forceinline__ u64 shx2(u64 v, int d) {
    return __shfl_xor_sync(0xffffffffu, v, d);
}

// ---- cluster helpers ----
__device__ __forceinline__ void cluster_sync_() {
    asm volatile("barrier.cluster.arrive.aligned;" ::: "memory");
    asm volatile("barrier.cluster.wait.aligned;"   ::: "memory");
}
__device__ __forceinline__ uint32_t smem_u32(const void* p) {
    uint32_t a;
    asm("{ .reg .u64 t; cvta.to.shared.u64 t, %1; cvt.u32.u64 %0, t; }" : "=r"(a) : "l"(p));
    return a;
}
__device__ __forceinline__ float cluster_ld_f32(uint32_t laddr, uint32_t rank) {
    uint32_t ra; float v;
    asm("mapa.shared::cluster.u32 %0, %1, %2;" : "=r"(ra) : "r"(laddr), "r"(rank));
    asm volatile("ld.shared::cluster.f32 %0, [%1];" : "=f"(v) : "r"(ra) : "memory");
    return v;
}

__device__ __forceinline__ int bitrev4(int x) {
    return ((x&1)<<3) | (((x>>1)&1)<<2) | (((x>>2)&1)<<1) | ((x>>3)&1);
}

// SEL-free permuted dual reduction: yV/yV2 are 8 u64 each; lane L placed
// slot (L&7)^bitrev3(j) at position j. After stages, lane L's yV[0]/yV2[0]
// hold the full 32-lane sums (pair lo/hi = r parity) for (p,rp)=((L>>1)&3, L&1).
__device__ __forceinline__ void reduce8x2(u64 (&yV)[8], u64 (&yV2)[8])
{
#pragma unroll
    for (int j = 0; j < 4; j++) {
        yV [j] = add2(yV [j], shx2(yV [j+4], 1));
        yV2[j] = add2(yV2[j], shx2(yV2[j+4], 1));
    }
#pragma unroll
    for (int j = 0; j < 2; j++) {
        yV [j] = add2(yV [j], shx2(yV [j+2], 2));
        yV2[j] = add2(yV2[j], shx2(yV2[j+2], 2));
    }
    yV [0] = add2(yV [0], shx2(yV [1], 4));
    yV2[0] = add2(yV2[0], shx2(yV2[1], 4));
    yV [0] = add2(yV [0], shx2(yV [0], 8));
    yV2[0] = add2(yV2[0], shx2(yV2[0], 8));
    yV [0] = add2(yV [0], shx2(yV [0], 16));
    yV2[0] = add2(yV2[0], shx2(yV2[0], 16));
}

// 16 scalars across 32 lanes (R); lane owns bitrev4(lane&15).
__device__ __forceinline__ float reduce16_to_lane(float (&y)[16], int lane)
{
#pragma unroll
    for (int j = 0; j < 8; j++) {
        bool up = lane & 1;
        float s = up ? y[j] : y[j+8];
        float k = up ? y[j+8] : y[j];
        y[j] = k + __shfl_xor_sync(0xffffffffu, s, 1);
    }
#pragma unroll
    for (int j = 0; j < 4; j++) {
        bool up = lane & 2;
        float s = up ? y[j] : y[j+4];
        float k = up ? y[j+4] : y[j];
        y[j] = k + __shfl_xor_sync(0xffffffffu, s, 2);
    }
#pragma unroll
    for (int j = 0; j < 2; j++) {
        bool up = lane & 4;
        float s = up ? y[j] : y[j+2];
        float k = up ? y[j+2] : y[j];
        y[j] = k + __shfl_xor_sync(0xffffffffu, s, 4);
    }
    {
        bool up = lane & 8;
        float s = up ? y[0] : y[1];
        float k = up ? y[1] : y[0];
        y[0] = k + __shfl_xor_sync(0xffffffffu, s, 8);
    }
    y[0] += __shfl_xor_sync(0xffffffffu, y[0], 16);
    return y[0];
}

// compile-time position constants: cj = p-block register group, BR3 = slot xor
#define CJ(j)  ((((j)&1)<<1) | (((j)>>1)&1))
#define BR3(j) (((((j)&1))<<2) | ((j)&2) | (((j)>>2)&1))

// ======================= the single fused kernel =======================
__global__ __cluster_dims__(4,1,1) __launch_bounds__(THREADS,1)
void k_mega(const float* __restrict__ l, const float* __restrict__ g,
            const float* __restrict__ w, const float* __restrict__ beta_a,
            const float* __restrict__ beta_u, float* __restrict__ out)
{
    __shared__ alignas(16) float w_sh[CPB*160];
    __shared__ alignas(16) float ep_sh[MM*32];   // [m][u][i2lo,i2hi,mu2nlo,mu2nhi]
    __shared__ float K_sh[10], a_sh[10], Rtot[10];
    __shared__ float acc1[160], acc2[160], accR[16];

    const int tid = threadIdx.x, lane = tid & 31;
    const int crank = blockIdx.x & 3;
    const int n     = blockIdx.x >> 2;

    const int Lp = (lane >> 1) & 3;   // p permute bits
    const int L0 = lane & 1;          // rp permute bit
    const int L7 = lane & 7;

    for (int i = tid; i < CPB*160; i += THREADS)
        w_sh[i] = w[(crank*CPB)*160 + i];
    if (tid < 160) { acc1[tid] = 0.f; acc2[tid] = 0.f; }
    if (tid < 16)  accR[tid] = 0.f;
    __syncthreads();

    // lane-owned final scalar: d = 4p + 2rp + hi, array = vv ? acc2 : acc1
    float* accp = (((lane>>3)&1) ? acc2 : acc1) + 4*Lp + 2*L0 + ((lane>>4)&1);

    const uint32_t a1addr = smem_u32(&acc1[tid < 160 ? tid : 0]);
    const uint32_t a2addr = smem_u32(&acc2[tid < 160 ? tid : 0]);
    const uint32_t aRaddr = smem_u32(&accR[tid < 16  ? tid : 0]);

    const int em = (tid < 160) ? (tid >> 4) : 0;
    const int ed = tid & 15;
    const float ba = beta_a[em], bu = beta_u[em];

    // ================= PASS A: S1 = sum V, S2 = sum V^2 =================
    for (int item = tid; item < ITEMS; item += THREADS) {
        const int cl = item / SSZ, s = item - cl*SSZ;
        const float* lbase = l + ((size_t)(n*CC + crank*CPB + cl)*16)*SSZ + s;
        u64 lvp[16];
#pragma unroll
        for (int i = 0; i < 16; i++) {
            int d = 4*((i>>2) ^ Lp) + (i&3);
            lvp[i] = bc2(lbase[d*SSZ]);
        }

#pragma unroll
        for (int m = 0; m < MM; m++) {
            const float* wm = &w_sh[cl*160 + m*16];
            u64 wA[4], wB[4];
#pragma unroll
            for (int q = 0; q < 4; q++) {
                wA[q] = *(const u64*)(wm + 4*q + 2*L0);
                wB[q] = *(const u64*)(wm + 4*q + 2*(L0^1));
            }
            u64 yV[8], yV2[8];
#pragma unroll
            for (int j = 0; j < 8; j++) {
                const int cj = CJ(j);
                const u64* wc = (j < 4) ? wA : wB;
                u64 v = fma2(lvp[4*cj],   wc[0],
                        fma2(lvp[4*cj+1], wc[1],
                        fma2(lvp[4*cj+2], wc[2],
                        mul2(lvp[4*cj+3], wc[3]))));
                yV[j]  = v;
                yV2[j] = mul2(v, v);
            }
            reduce8x2(yV, yV2);
            u64 mine = ((lane>>3)&1) ? yV2[0] : yV[0];
            float lo, hi; upk(mine, lo, hi);
            atomicAdd(accp + m*16, ((lane>>4)&1) ? hi : lo);
        }
    }
    __syncthreads();
    cluster_sync_();

    // ----- combine S1/S2 across the 4 CTAs -----
    float S1 = 0.f, S2 = 0.f;
    if (tid < 160) {
#pragma unroll
        for (uint32_t rk = 0; rk < 4; rk++) {
            S1 += cluster_ld_f32(a1addr, rk);
            S2 += cluster_ld_f32(a2addr, rk);
        }
    }
    cluster_sync_();
    if (tid < 160) { acc1[tid] = 0.f; acc2[tid] = 0.f; }

    // ----- epilogue A -----
    if (tid < 160) {
        float gv = g[(n*MM + em)*16 + ed];
        float sig0 = S2 - 2.f*gv*S1 + BBF*gv*gv + EPSF;
        float sl = logf(sig0);
#pragma unroll
        for (int o = 8; o > 0; o >>= 1) sl += __shfl_xor_sync(0xffffffffu, sl, o);

        float a0 = 1.f / (1.f + expf(-(LAM_INIT * (ba - 16.f*bu - 0.5f*sl))));
        float rsum  = BBF * a0 * 0.1f;
        float coeff = (a0 * 0.1f) / (rsum + EPSF);
        float mu    = coeff * S1;
        float sig   = coeff * (S2 - 2.f*mu*S1 + BBF*mu*mu) + EPSF;
        float sl2 = logf(sig);
#pragma unroll
        for (int o = 8; o > 0; o >>= 1) sl2 += __shfl_xor_sync(0xffffffffu, sl2, o);

        float logit = LAM_ROUT * (ba - rsum * (16.f*bu + 0.5f*sl2));
        float a1 = 1.f / (1.f + expf(-logit));

        float i2  = 0.5f / sig;
        float cst = mu*mu*i2;
#pragma unroll
        for (int o = 8; o > 0; o >>= 1) cst += __shfl_xor_sync(0xffffffffu, cst, o);

        ep_sh[em*32 + (ed>>1)*4 +     (ed&1)] = i2;
        ep_sh[em*32 + (ed>>1)*4 + 2 + (ed&1)] = -(mu / sig);
        if (ed == 0) {
            a_sh[em] = a1;
            K_sh[em] = -0.5f*sl2 - 8.f*LN2PI + logf(a1) - cst;
        }
    }
    __syncthreads();

    // ================= routing iterations 1 and 2 =================
    for (int it = 0; it < 2; it++) {
        for (int item = tid; item < ITEMS; item += THREADS) {
            const int cl = item / SSZ, s = item - cl*SSZ;
            const float* lbase = l + ((size_t)(n*CC + crank*CPB + cl)*16)*SSZ + s;
            u64 lvp[16];
#pragma unroll
            for (int i = 0; i < 16; i++) {
                int d = 4*((i>>2) ^ Lp) + (i&3);
                lvp[i] = bc2(lbase[d*SSZ]);
            }

            // ---- E-step ----
            float lnap[10];
#pragma unroll
            for (int m = 0; m < MM; m++) {
                const float* wm = &w_sh[cl*160 + m*16];
                u64 wA[4], wB[4];
#pragma unroll
                for (int q = 0; q < 4; q++) {
                    wA[q] = *(const u64*)(wm + 4*q + 2*L0);
                    wB[q] = *(const u64*)(wm + 4*q + 2*(L0^1));
                }
                u64 qacc = 0ull;
#pragma unroll
                for (int j = 0; j < 8; j++) {
                    const int cj = CJ(j);
                    const u64* wc = (j < 4) ? wA : wB;
                    u64 v = fma2(lvp[4*cj],   wc[0],
                            fma2(lvp[4*cj+1], wc[1],
                            fma2(lvp[4*cj+2], wc[2],
                            mul2(lvp[4*cj+3], wc[3]))));
                    const int u = L7 ^ BR3(j);
                    ulonglong2 ep = *(const ulonglong2*)&ep_sh[m*32 + u*4];
                    u64 t1 = fma2(v, ep.x, ep.y);
                    qacc = fma2(v, t1, qacc);
                }
                float ql, qh; upk(qacc, ql, qh);
                lnap[m] = K_sh[m] - (ql + qh);
            }

            // stable softmax * a
            float mx = lnap[0];
#pragma unroll
            for (int m = 1; m < MM; m++) mx = fmaxf(mx, lnap[m]);
            float den = 0.f;
#pragma unroll
            for (int m = 0; m < MM; m++) { lnap[m] = __expf(lnap[m] - mx); den += lnap[m]; }
            float sc = 1.f / den;
#pragma unroll
            for (int m = 0; m < MM; m++) lnap[m] = lnap[m] * sc * a_sh[m];

            // ---- M-step statistics ----
#pragma unroll
            for (int m = 0; m < MM; m++) {
                const float* wm = &w_sh[cl*160 + m*16];
                u64 wA[4], wB[4];
#pragma unroll
                for (int q = 0; q < 4; q++) {
                    wA[q] = *(const u64*)(wm + 4*q + 2*L0);
                    wB[q] = *(const u64*)(wm + 4*q + 2*(L0^1));
                }
                u64 rmp = bc2(lnap[m]);
                u64 yV[8], yV2[8];
#pragma unroll
                for (int j = 0; j < 8; j++) {
                    const int cj = CJ(j);
                    const u64* wc = (j < 4) ? wA : wB;
                    u64 v = fma2(lvp[4*cj],   wc[0],
                            fma2(lvp[4*cj+1], wc[1],
                            fma2(lvp[4*cj+2], wc[2],
                            mul2(lvp[4*cj+3], wc[3]))));
                    u64 c1 = mul2(rmp, v);
                    yV[j]  = c1;
                    yV2[j] = mul2(c1, v);
                }
                reduce8x2(yV, yV2);
                u64 mine = ((lane>>3)&1) ? yV2[0] : yV[0];
                float lo, hi; upk(mine, lo, hi);
                atomicAdd(accp + m*16, ((lane>>4)&1) ? hi : lo);
            }
            // R sums
            {
                float y[16];
#pragma unroll
                for (int m = 0; m < MM; m++) y[m] = lnap[m];
#pragma unroll
                for (int m = MM; m < 16; m++) y[m] = 0.f;
                float val = reduce16_to_lane(y, lane);
                int idx4 = bitrev4(lane & 15);
                if (lane < 16 && idx4 < MM) atomicAdd(&accR[idx4], val);
            }
        }
        __syncthreads();
        cluster_sync_();

        // combine A1/A2/R across CTAs
        float A1 = 0.f, A2 = 0.f, R = 0.f;
        if (tid < 160) {
#pragma unroll
            for (uint32_t rk = 0; rk < 4; rk++) {
                A1 += cluster_ld_f32(a1addr, rk);
                A2 += cluster_ld_f32(a2addr, rk);
            }
        }
        if (tid < 16) {
#pragma unroll
            for (uint32_t rk = 0; rk < 4; rk++) R += cluster_ld_f32(aRaddr, rk);
        }
        cluster_sync_();
        if (tid < 160) { acc1[tid] = 0.f; acc2[tid] = 0.f; }
        if (tid < 16)  accR[tid] = 0.f;
        if (tid < 10)  Rtot[tid] = R;
        __syncthreads();

        if (tid < 160) {
            float Rm  = Rtot[em];
            float inv = 1.f / (Rm + EPSF);
            float mu  = A1 * inv;
            float sig = (A2 - 2.f*mu*A1 + mu*mu*Rm) * inv + EPSF;
            float sl  = logf(sig);
#pragma unroll
            for (int o = 8; o > 0; o >>= 1) sl += __shfl_xor_sync(0xffffffffu, sl, o);

            float logit = LAM_ROUT * (ba - Rm * (16.f*bu + 0.5f*sl));
            float a = 1.f / (1.f + expf(-logit));

            if (it == 0) {
                float i2  = 0.5f / sig;
                float cst = mu*mu*i2;
#pragma unroll
                for (int o = 8; o > 0; o >>= 1) cst += __shfl_xor_sync(0xffffffffu, cst, o);
                ep_sh[em*32 + (ed>>1)*4 +     (ed&1)] = i2;
                ep_sh[em*32 + (ed>>1)*4 + 2 + (ed&1)] = -(mu / sig);
                if (ed == 0) {
                    a_sh[em] = a;
                    K_sh[em] = -0.5f*sl - 8.f*LN2PI + logf(a) - cst;
                }
            } else if (crank == 0) {
                out[NN*MM + n*160 + tid] = mu;          // mu block (N, M, 16)
                if (ed == 0) out[n*MM + em] = a;        // a_out block (N, M)
            }
        }
        __syncthreads();
    }
}

extern "C" void kernel_launch(void* const* d_in, const int* in_sizes, int n_in,
                              void* d_out, int out_size)
{
    const float* l      = (const float*)d_in[0];
    const float* g      = (const float*)d_in[1];
    const float* weight = (const float*)d_in[2];
    const float* beta_a = (const float*)d_in[3];
    const float* beta_u = (const float*)d_in[4];
    float* out = (float*)d_out;

    k_mega<<<NN*4, THREADS>>>(l, g, weight, beta_a, beta_u, out);

    (void)in_sizes; (void)n_in; (void)out_size;
}

// round 9
// speedup vs baseline: 5.6705x; 1.1620x over previous
#include <cuda_runtime.h>
#include <math.h>
#include <stdint.h>

#define NN 32
#define CC 32
#define MM 10
#define SSZ 196
#define CPB 8                 // channels per CTA
#define ITEMS (CPB*SSZ)       // 1568 items per CTA
#define NPAIRS (ITEMS/2)      // 784 item-pairs per CTA
#define THREADS 448
#define NITER ((NPAIRS + THREADS - 1) / THREADS)   // 2, uniform for all threads
#define BBF 6272.0f
#define EPSF 1e-6f
#define LAM_INIT 0.001f
#define LAM_ROUT 0.001f
#define LN2PI 1.8378770664093453f

typedef unsigned long long u64;

// ---- packed f32x2 helpers ----
__device__ __forceinline__ u64 pk2(float lo, float hi) {
    u64 r; asm("mov.b64 %0, {%1,%2};" : "=l"(r) : "f"(lo), "f"(hi)); return r;
}
__device__ __forceinline__ u64 bc2(float x) { return pk2(x, x); }
__device__ __forceinline__ void upk(u64 v, float& lo, float& hi) {
    asm("mov.b64 {%0,%1}, %2;" : "=f"(lo), "=f"(hi) : "l"(v));
}
__device__ __forceinline__ u64 fma2(u64 a, u64 b, u64 c) {
    u64 d; asm("fma.rn.f32x2 %0, %1, %2, %3;" : "=l"(d) : "l"(a), "l"(b), "l"(c)); return d;
}
__device__ __forceinline__ u64 mul2(u64 a, u64 b) {
    u64 d; asm("mul.rn.f32x2 %0, %1, %2;" : "=l"(d) : "l"(a), "l"(b)); return d;
}
__device__ __forceinline__ u64 add2(u64 a, u64 b) {
    u64 d; asm("add.rn.f32x2 %0, %1, %2;" : "=l"(d) : "l"(a), "l"(b)); return d;
}
__device__ __forceinline__ u64 shx2(u64 v, int d) {
    return __shfl_xor_sync(0xffffffffu, v, d);
}

// ---- cluster helpers ----
__device__ __forceinline__ void cluster_sync_() {
    asm volatile("barrier.cluster.arrive.aligned;" ::: "memory");
    asm volatile("barrier.cluster.wait.aligned;"   ::: "memory");
}
__device__ __forceinline__ uint32_t smem_u32(const void* p) {
    uint32_t a;
    asm("{ .reg .u64 t; cvta.to.shared.u64 t, %1; cvt.u32.u64 %0, t; }" : "=r"(a) : "l"(p));
    return a;
}
__device__ __forceinline__ float cluster_ld_f32(uint32_t laddr, uint32_t rank) {
    uint32_t ra; float v;
    asm("mapa.shared::cluster.u32 %0, %1, %2;" : "=r"(ra) : "r"(laddr), "r"(rank));
    asm volatile("ld.shared::cluster.f32 %0, [%1];" : "=f"(v) : "r"(ra) : "memory");
    return v;
}

__device__ __forceinline__ int bitrev4(int x) {
    return ((x&1)<<3) | (((x>>1)&1)<<2) | (((x>>2)&1)<<1) | ((x>>3)&1);
}

// SEL-free permuted dual reduction (see R7): lane L placed slot (L&7)^bitrev3(j)
// at position j. After stages, lane L's yV[0]/yV2[0] hold the 32-lane sums
// (pair lo/hi = r parity) for (p,rp)=((L>>1)&3, L&1).
__device__ __forceinline__ void reduce8x2(u64 (&yV)[8], u64 (&yV2)[8])
{
#pragma unroll
    for (int j = 0; j < 4; j++) {
        yV [j] = add2(yV [j], shx2(yV [j+4], 1));
        yV2[j] = add2(yV2[j], shx2(yV2[j+4], 1));
    }
#pragma unroll
    for (int j = 0; j < 2; j++) {
        yV [j] = add2(yV [j], shx2(yV [j+2], 2));
        yV2[j] = add2(yV2[j], shx2(yV2[j+2], 2));
    }
    yV [0] = add2(yV [0], shx2(yV [1], 4));
    yV2[0] = add2(yV2[0], shx2(yV2[1], 4));
    yV [0] = add2(yV [0], shx2(yV [0], 8));
    yV2[0] = add2(yV2[0], shx2(yV2[0], 8));
    yV [0] = add2(yV [0], shx2(yV [0], 16));
    yV2[0] = add2(yV2[0], shx2(yV2[0], 16));
}

// 16 scalars across 32 lanes (R); lane owns bitrev4(lane&15).
__device__ __forceinline__ float reduce16_to_lane(float (&y)[16], int lane)
{
#pragma unroll
    for (int j = 0; j < 8; j++) {
        bool up = lane & 1;
        float s = up ? y[j] : y[j+8];
        float k = up ? y[j+8] : y[j];
        y[j] = k + __shfl_xor_sync(0xffffffffu, s, 1);
    }
#pragma unroll
    for (int j = 0; j < 4; j++) {
        bool up = lane & 2;
        float s = up ? y[j] : y[j+4];
        float k = up ? y[j+4] : y[j];
        y[j] = k + __shfl_xor_sync(0xffffffffu, s, 2);
    }
#pragma unroll
    for (int j = 0; j < 2; j++) {
        bool up = lane & 4;
        float s = up ? y[j] : y[j+2];
        float k = up ? y[j+2] : y[j];
        y[j] = k + __shfl_xor_sync(0xffffffffu, s, 4);
    }
    {
        bool up = lane & 8;
        float s = up ? y[0] : y[1];
        float k = up ? y[1] : y[0];
        y[0] = k + __shfl_xor_sync(0xffffffffu, s, 8);
    }
    y[0] += __shfl_xor_sync(0xffffffffu, y[0], 16);
    return y[0];
}

#define CJ(j)  ((((j)&1)<<1) | (((j)>>1)&1))
#define BR3(j) (((((j)&1))<<2) | ((j)&2) | (((j)>>2)&1))

// ======================= the single fused kernel =======================
__global__ __cluster_dims__(4,1,1) __launch_bounds__(THREADS,1)
void k_mega(const float* __restrict__ l, const float* __restrict__ g,
            const float* __restrict__ w, const float* __restrict__ beta_a,
            const float* __restrict__ beta_u, float* __restrict__ out)
{
    __shared__ alignas(16) float w_sh[CPB*160];
    __shared__ alignas(16) float ep_sh[MM*32];   // [m][u][i2lo,i2hi,mu2nlo,mu2nhi]
    __shared__ float K_sh[10], a_sh[10], Rtot[10];
    __shared__ float acc1[160], acc2[160], accR[16];

    const int tid = threadIdx.x, lane = tid & 31;
    const int crank = blockIdx.x & 3;
    const int n     = blockIdx.x >> 2;

    const int Lp = (lane >> 1) & 3;
    const int L0 = lane & 1;
    const int L7 = lane & 7;

    for (int i = tid; i < CPB*160; i += THREADS)
        w_sh[i] = w[(crank*CPB)*160 + i];
    if (tid < 160) { acc1[tid] = 0.f; acc2[tid] = 0.f; }
    if (tid < 16)  accR[tid] = 0.f;
    __syncthreads();

    float* accp = (((lane>>3)&1) ? acc2 : acc1) + 4*Lp + 2*L0 + ((lane>>4)&1);

    const uint32_t a1addr = smem_u32(&acc1[tid < 160 ? tid : 0]);
    const uint32_t a2addr = smem_u32(&acc2[tid < 160 ? tid : 0]);
    const uint32_t aRaddr = smem_u32(&accR[tid < 16  ? tid : 0]);

    const int em = (tid < 160) ? (tid >> 4) : 0;
    const int ed = tid & 15;
    const float ba = beta_a[em], bu = beta_u[em];

    // ================= PASS A: S1 = sum V, S2 = sum V^2 =================
#pragma unroll
    for (int k = 0; k < NITER; k++) {
        const int pr = tid + k*THREADS;
        const bool act = pr < NPAIRS;
        const int prc = act ? pr : 0;
        const int cl = prc / (SSZ/2), s = 2*prc - cl*SSZ;   // pair (s, s+1), same channel
        const float* lbase = l + ((size_t)(n*CC + crank*CPB + cl)*16)*SSZ + s;
        float2 lf[16];
#pragma unroll
        for (int i = 0; i < 16; i++) {
            int d = 4*((i>>2) ^ Lp) + (i&3);
            float2 t = *(const float2*)(lbase + d*SSZ);
            lf[i] = act ? t : make_float2(0.f, 0.f);
        }

#pragma unroll
        for (int m = 0; m < MM; m++) {
            const float* wm = &w_sh[cl*160 + m*16];
            u64 wA[4], wB[4];
#pragma unroll
            for (int q = 0; q < 4; q++) {
                wA[q] = *(const u64*)(wm + 4*q + 2*L0);
                wB[q] = *(const u64*)(wm + 4*q + 2*(L0^1));
            }
            u64 yV[8], yV2[8];
#pragma unroll
            for (int j = 0; j < 8; j++) {
                const int cj = CJ(j);
                const u64* wc = (j < 4) ? wA : wB;
                u64 vA = fma2(bc2(lf[4*cj].x),   wc[0],
                         fma2(bc2(lf[4*cj+1].x), wc[1],
                         fma2(bc2(lf[4*cj+2].x), wc[2],
                         mul2(bc2(lf[4*cj+3].x), wc[3]))));
                u64 vB = fma2(bc2(lf[4*cj].y),   wc[0],
                         fma2(bc2(lf[4*cj+1].y), wc[1],
                         fma2(bc2(lf[4*cj+2].y), wc[2],
                         mul2(bc2(lf[4*cj+3].y), wc[3]))));
                yV [j] = add2(vA, vB);
                yV2[j] = add2(mul2(vA, vA), mul2(vB, vB));
            }
            reduce8x2(yV, yV2);
            u64 mine = ((lane>>3)&1) ? yV2[0] : yV[0];
            float lo, hi; upk(mine, lo, hi);
            atomicAdd(accp + m*16, ((lane>>4)&1) ? hi : lo);
        }
    }
    __syncthreads();
    cluster_sync_();

    // ----- combine S1/S2 across the 4 CTAs -----
    float S1 = 0.f, S2 = 0.f;
    if (tid < 160) {
#pragma unroll
        for (uint32_t rk = 0; rk < 4; rk++) {
            S1 += cluster_ld_f32(a1addr, rk);
            S2 += cluster_ld_f32(a2addr, rk);
        }
    }
    cluster_sync_();
    if (tid < 160) { acc1[tid] = 0.f; acc2[tid] = 0.f; }

    // ----- epilogue A -----
    if (tid < 160) {
        float gv = g[(n*MM + em)*16 + ed];
        float sig0 = S2 - 2.f*gv*S1 + BBF*gv*gv + EPSF;
        float sl = logf(sig0);
#pragma unroll
        for (int o = 8; o > 0; o >>= 1) sl += __shfl_xor_sync(0xffffffffu, sl, o);

        float a0 = 1.f / (1.f + expf(-(LAM_INIT * (ba - 16.f*bu - 0.5f*sl))));
        float rsum  = BBF * a0 * 0.1f;
        float coeff = (a0 * 0.1f) / (rsum + EPSF);
        float mu    = coeff * S1;
        float sig   = coeff * (S2 - 2.f*mu*S1 + BBF*mu*mu) + EPSF;
        float sl2 = logf(sig);
#pragma unroll
        for (int o = 8; o > 0; o >>= 1) sl2 += __shfl_xor_sync(0xffffffffu, sl2, o);

        float logit = LAM_ROUT * (ba - rsum * (16.f*bu + 0.5f*sl2));
        float a1 = 1.f / (1.f + expf(-logit));

        float i2  = 0.5f / sig;
        float cst = mu*mu*i2;
#pragma unroll
        for (int o = 8; o > 0; o >>= 1) cst += __shfl_xor_sync(0xffffffffu, cst, o);

        ep_sh[em*32 + (ed>>1)*4 +     (ed&1)] = i2;
        ep_sh[em*32 + (ed>>1)*4 + 2 + (ed&1)] = -(mu / sig);
        if (ed == 0) {
            a_sh[em] = a1;
            K_sh[em] = -0.5f*sl2 - 8.f*LN2PI + logf(a1) - cst;
        }
    }
    __syncthreads();

    // ================= routing iterations 1 and 2 =================
    for (int it = 0; it < 2; it++) {
#pragma unroll
        for (int k = 0; k < NITER; k++) {
            const int pr = tid + k*THREADS;
            const bool act = pr < NPAIRS;
            const int prc = act ? pr : 0;
            const int cl = prc / (SSZ/2), s = 2*prc - cl*SSZ;
            const float* lbase = l + ((size_t)(n*CC + crank*CPB + cl)*16)*SSZ + s;
            float2 lf[16];
#pragma unroll
            for (int i = 0; i < 16; i++) {
                int d = 4*((i>>2) ^ Lp) + (i&3);
                float2 t = *(const float2*)(lbase + d*SSZ);
                lf[i] = act ? t : make_float2(0.f, 0.f);
            }

            // ---- E-step: both items ----
            float lnapA[10], lnapB[10];
#pragma unroll
            for (int m = 0; m < MM; m++) {
                const float* wm = &w_sh[cl*160 + m*16];
                u64 wA[4], wB[4];
#pragma unroll
                for (int q = 0; q < 4; q++) {
                    wA[q] = *(const u64*)(wm + 4*q + 2*L0);
                    wB[q] = *(const u64*)(wm + 4*q + 2*(L0^1));
                }
                u64 qA = 0ull, qB = 0ull;
#pragma unroll
                for (int j = 0; j < 8; j++) {
                    const int cj = CJ(j);
                    const u64* wc = (j < 4) ? wA : wB;
                    const int u = L7 ^ BR3(j);
                    ulonglong2 ep = *(const ulonglong2*)&ep_sh[m*32 + u*4];
                    u64 vA = fma2(bc2(lf[4*cj].x),   wc[0],
                             fma2(bc2(lf[4*cj+1].x), wc[1],
                             fma2(bc2(lf[4*cj+2].x), wc[2],
                             mul2(bc2(lf[4*cj+3].x), wc[3]))));
                    u64 vB = fma2(bc2(lf[4*cj].y),   wc[0],
                             fma2(bc2(lf[4*cj+1].y), wc[1],
                             fma2(bc2(lf[4*cj+2].y), wc[2],
                             mul2(bc2(lf[4*cj+3].y), wc[3]))));
                    qA = fma2(vA, fma2(vA, ep.x, ep.y), qA);
                    qB = fma2(vB, fma2(vB, ep.x, ep.y), qB);
                }
                float ql, qh;
                upk(qA, ql, qh); lnapA[m] = K_sh[m] - (ql + qh);
                upk(qB, ql, qh); lnapB[m] = K_sh[m] - (ql + qh);
            }

            // stable softmax * a, both items; inactive threads masked to 0
            {
                float mxA = lnapA[0], mxB = lnapB[0];
#pragma unroll
                for (int m = 1; m < MM; m++) { mxA = fmaxf(mxA, lnapA[m]); mxB = fmaxf(mxB, lnapB[m]); }
                float dA = 0.f, dB = 0.f;
#pragma unroll
                for (int m = 0; m < MM; m++) {
                    lnapA[m] = __expf(lnapA[m] - mxA); dA += lnapA[m];
                    lnapB[m] = __expf(lnapB[m] - mxB); dB += lnapB[m];
                }
                float sA = act ? (1.f / dA) : 0.f;
                float sB = act ? (1.f / dB) : 0.f;
#pragma unroll
                for (int m = 0; m < MM; m++) {
                    lnapA[m] = lnapA[m] * sA * a_sh[m];
                    lnapB[m] = lnapB[m] * sB * a_sh[m];
                }
            }

            // ---- M-step statistics: pair-accumulated before reduction ----
#pragma unroll
            for (int m = 0; m < MM; m++) {
                const float* wm = &w_sh[cl*160 + m*16];
                u64 wA[4], wB[4];
#pragma unroll
                for (int q = 0; q < 4; q++) {
                    wA[q] = *(const u64*)(wm + 4*q + 2*L0);
                    wB[q] = *(const u64*)(wm + 4*q + 2*(L0^1));
                }
                u64 rA = bc2(lnapA[m]), rB = bc2(lnapB[m]);
                u64 yV[8], yV2[8];
#pragma unroll
                for (int j = 0; j < 8; j++) {
                    const int cj = CJ(j);
                    const u64* wc = (j < 4) ? wA : wB;
                    u64 vA = fma2(bc2(lf[4*cj].x),   wc[0],
                             fma2(bc2(lf[4*cj+1].x), wc[1],
                             fma2(bc2(lf[4*cj+2].x), wc[2],
                             mul2(bc2(lf[4*cj+3].x), wc[3]))));
                    u64 vB = fma2(bc2(lf[4*cj].y),   wc[0],
                             fma2(bc2(lf[4*cj+1].y), wc[1],
                             fma2(bc2(lf[4*cj+2].y), wc[2],
                             mul2(bc2(lf[4*cj+3].y), wc[3]))));
                    u64 cA = mul2(rA, vA), cB = mul2(rB, vB);
                    yV [j] = add2(cA, cB);
                    yV2[j] = add2(mul2(cA, vA), mul2(cB, vB));
                }
                reduce8x2(yV, yV2);
                u64 mine = ((lane>>3)&1) ? yV2[0] : yV[0];
                float lo, hi; upk(mine, lo, hi);
                atomicAdd(accp + m*16, ((lane>>4)&1) ? hi : lo);
            }
            // R sums (pair-summed)
            {
                float y[16];
#pragma unroll
                for (int m = 0; m < MM; m++) y[m] = lnapA[m] + lnapB[m];
#pragma unroll
                for (int m = MM; m < 16; m++) y[m] = 0.f;
                float val = reduce16_to_lane(y, lane);
                int idx4 = bitrev4(lane & 15);
                if (lane < 16 && idx4 < MM) atomicAdd(&accR[idx4], val);
            }
        }
        __syncthreads();
        cluster_sync_();

        // combine A1/A2/R across CTAs
        float A1 = 0.f, A2 = 0.f, R = 0.f;
        if (tid < 160) {
#pragma unroll
            for (uint32_t rk = 0; rk < 4; rk++) {
                A1 += cluster_ld_f32(a1addr, rk);
                A2 += cluster_ld_f32(a2addr, rk);
            }
        }
        if (tid < 16) {
#pragma unroll
            for (uint32_t rk = 0; rk < 4; rk++) R += cluster_ld_f32(aRaddr, rk);
        }
        cluster_sync_();
        if (tid < 160) { acc1[tid] = 0.f; acc2[tid] = 0.f; }
        if (tid < 16)  accR[tid] = 0.f;
        if (tid < 10)  Rtot[tid] = R;
        __syncthreads();

        if (tid < 160) {
            float Rm  = Rtot[em];
            float inv = 1.f / (Rm + EPSF);
            float mu  = A1 * inv;
            float sig = (A2 - 2.f*mu*A1 + mu*mu*Rm) * inv + EPSF;
            float sl  = logf(sig);
#pragma unroll
            for (int o = 8; o > 0; o >>= 1) sl += __shfl_xor_sync(0xffffffffu, sl, o);

            float logit = LAM_ROUT * (ba - Rm * (16.f*bu + 0.5f*sl));
            float a = 1.f / (1.f + expf(-logit));

            if (it == 0) {
                float i2  = 0.5f / sig;
                float cst = mu*mu*i2;
#pragma unroll
                for (int o = 8; o > 0; o >>= 1) cst += __shfl_xor_sync(0xffffffffu, cst, o);
                ep_sh[em*32 + (ed>>1)*4 +     (ed&1)] = i2;
                ep_sh[em*32 + (ed>>1)*4 + 2 + (ed&1)] = -(mu / sig);
                if (ed == 0) {
                    a_sh[em] = a;
                    K_sh[em] = -0.5f*sl - 8.f*LN2PI + logf(a) - cst;
                }
            } else if (crank == 0) {
                out[NN*MM + n*160 + tid] = mu;          // mu block (N, M, 16)
                if (ed == 0) out[n*MM + em] = a;        // a_out block (N, M)
            }
        }
        __syncthreads();
    }
}

extern "C" void kernel_launch(void* const* d_in, const int* in_sizes, int n_in,
                              void* d_out, int out_size)
{
    const float* l      = (const float*)d_in[0];
    const float* g      = (const float*)d_in[1];
    const float* weight = (const float*)d_in[2];
    const float* beta_a = (const float*)d_in[3];
    const float* beta_u = (const float*)d_in[4];
    float* out = (float*)d_out;

    k_mega<<<NN*4, THREADS>>>(l, g, weight, beta_a, beta_u, out);

    (void)in_sizes; (void)n_in; (void)out_size;
}

// round 10
// speedup vs baseline: 6.1760x; 1.0892x over previous
#include <cuda_runtime.h>
#include <math.h>
#include <stdint.h>

#define NN 32
#define CC 32
#define MM 10
#define SSZ 196
#define CPB 8                 // channels per CTA
#define ITEMS (CPB*SSZ)       // 1568 items per CTA
#define NPAIRS (ITEMS/2)      // 784 item-pairs per CTA
#define THREADS 448
#define NITER ((NPAIRS + THREADS - 1) / THREADS)   // 2, uniform for all threads
#define BBF 6272.0f
#define EPSF 1e-6f
#define LAM_INIT 0.001f
#define LAM_ROUT 0.001f
#define LN2PI 1.8378770664093453f

typedef unsigned long long u64;

// ---- packed f32x2 helpers ----
__device__ __forceinline__ u64 pk2(float lo, float hi) {
    u64 r; asm("mov.b64 %0, {%1,%2};" : "=l"(r) : "f"(lo), "f"(hi)); return r;
}
__device__ __forceinline__ u64 bc2(float x) { return pk2(x, x); }
__device__ __forceinline__ void upk(u64 v, float& lo, float& hi) {
    asm("mov.b64 {%0,%1}, %2;" : "=f"(lo), "=f"(hi) : "l"(v));
}
__device__ __forceinline__ u64 fma2(u64 a, u64 b, u64 c) {
    u64 d; asm("fma.rn.f32x2 %0, %1, %2, %3;" : "=l"(d) : "l"(a), "l"(b), "l"(c)); return d;
}
__device__ __forceinline__ u64 mul2(u64 a, u64 b) {
    u64 d; asm("mul.rn.f32x2 %0, %1, %2;" : "=l"(d) : "l"(a), "l"(b)); return d;
}
__device__ __forceinline__ u64 add2(u64 a, u64 b) {
    u64 d; asm("add.rn.f32x2 %0, %1, %2;" : "=l"(d) : "l"(a), "l"(b)); return d;
}
__device__ __forceinline__ u64 shx2(u64 v, int d) {
    return __shfl_xor_sync(0xffffffffu, v, d);
}

// ---- cluster helpers ----
__device__ __forceinline__ void cluster_sync_() {
    asm volatile("barrier.cluster.arrive.aligned;" ::: "memory");
    asm volatile("barrier.cluster.wait.aligned;"   ::: "memory");
}
__device__ __forceinline__ uint32_t smem_u32(const void* p) {
    uint32_t a;
    asm("{ .reg .u64 t; cvta.to.shared.u64 t, %1; cvt.u32.u64 %0, t; }" : "=r"(a) : "l"(p));
    return a;
}
__device__ __forceinline__ float cluster_ld_f32(uint32_t laddr, uint32_t rank) {
    uint32_t ra; float v;
    asm("mapa.shared::cluster.u32 %0, %1, %2;" : "=r"(ra) : "r"(laddr), "r"(rank));
    asm volatile("ld.shared::cluster.f32 %0, [%1];" : "=f"(v) : "r"(ra) : "memory");
    return v;
}

__device__ __forceinline__ int bitrev4(int x) {
    return ((x&1)<<3) | (((x>>1)&1)<<2) | (((x>>2)&1)<<1) | ((x>>3)&1);
}

// SEL-free permuted dual reduction (see R7): lane L placed slot (L&7)^bitrev3(j)
// at position j. After stages, lane L's yV[0]/yV2[0] hold the 32-lane sums;
// lane selects array by bit3, lo/hi by bit4, slot = lane&7.
__device__ __forceinline__ void reduce8x2(u64 (&yV)[8], u64 (&yV2)[8])
{
#pragma unroll
    for (int j = 0; j < 4; j++) {
        yV [j] = add2(yV [j], shx2(yV [j+4], 1));
        yV2[j] = add2(yV2[j], shx2(yV2[j+4], 1));
    }
#pragma unroll
    for (int j = 0; j < 2; j++) {
        yV [j] = add2(yV [j], shx2(yV [j+2], 2));
        yV2[j] = add2(yV2[j], shx2(yV2[j+2], 2));
    }
    yV [0] = add2(yV [0], shx2(yV [1], 4));
    yV2[0] = add2(yV2[0], shx2(yV2[1], 4));
    yV [0] = add2(yV [0], shx2(yV [0], 8));
    yV2[0] = add2(yV2[0], shx2(yV2[0], 8));
    yV [0] = add2(yV [0], shx2(yV [0], 16));
    yV2[0] = add2(yV2[0], shx2(yV2[0], 16));
}

// 16 scalars across 32 lanes (R); lane owns bitrev4(lane&15).
__device__ __forceinline__ float reduce16_to_lane(float (&y)[16], int lane)
{
#pragma unroll
    for (int j = 0; j < 8; j++) {
        bool up = lane & 1;
        float s = up ? y[j] : y[j+8];
        float k = up ? y[j+8] : y[j];
        y[j] = k + __shfl_xor_sync(0xffffffffu, s, 1);
    }
#pragma unroll
    for (int j = 0; j < 4; j++) {
        bool up = lane & 2;
        float s = up ? y[j] : y[j+4];
        float k = up ? y[j+4] : y[j];
        y[j] = k + __shfl_xor_sync(0xffffffffu, s, 2);
    }
#pragma unroll
    for (int j = 0; j < 2; j++) {
        bool up = lane & 4;
        float s = up ? y[j] : y[j+2];
        float k = up ? y[j+2] : y[j];
        y[j] = k + __shfl_xor_sync(0xffffffffu, s, 4);
    }
    {
        bool up = lane & 8;
        float s = up ? y[0] : y[1];
        float k = up ? y[1] : y[0];
        y[0] = k + __shfl_xor_sync(0xffffffffu, s, 8);
    }
    y[0] += __shfl_xor_sync(0xffffffffu, y[0], 16);
    return y[0];
}

#define CJ(j)  ((((j)&1)<<1) | (((j)>>1)&1))
#define BR3(j) (((((j)&1))<<2) | ((j)&2) | (((j)>>2)&1))

// ======================= the single fused kernel =======================
__global__ __cluster_dims__(4,1,1) __launch_bounds__(THREADS,1)
void k_mega(const float* __restrict__ l, const float* __restrict__ g,
            const float* __restrict__ w, const float* __restrict__ beta_a,
            const float* __restrict__ beta_u, float* __restrict__ out)
{
    __shared__ alignas(16) float w_sh[CPB*160];
    __shared__ alignas(16) float ep_sh[MM*32];   // [m][u][i2lo,i2hi,mu2nlo,mu2nhi]
    __shared__ alignas(16) float Ush[CPB*64];    // per-channel l-statistics (pass A)
    __shared__ float K_sh[10], a_sh[10], Rtot[10];
    __shared__ float acc1[160], acc2[160], accR[16];

    const int tid = threadIdx.x, lane = tid & 31;
    const int crank = blockIdx.x & 3;
    const int n     = blockIdx.x >> 2;

    const int Lp = (lane >> 1) & 3;
    const int L0 = lane & 1;
    const int L7 = lane & 7;

    for (int i = tid; i < CPB*160; i += THREADS)
        w_sh[i] = w[(crank*CPB)*160 + i];
    for (int i = tid; i < CPB*64; i += THREADS)
        Ush[i] = 0.f;
    if (tid < 160) { acc1[tid] = 0.f; acc2[tid] = 0.f; }
    if (tid < 16)  accR[tid] = 0.f;
    __syncthreads();

    float* accp = (((lane>>3)&1) ? acc2 : acc1) + 4*Lp + 2*L0 + ((lane>>4)&1);

    const uint32_t a1addr = smem_u32(&acc1[tid < 160 ? tid : 0]);
    const uint32_t a2addr = smem_u32(&acc2[tid < 160 ? tid : 0]);
    const uint32_t aRaddr = smem_u32(&accR[tid < 16  ? tid : 0]);

    const int em = (tid < 160) ? (tid >> 4) : 0;
    const int ed = tid & 15;
    const float ba = beta_a[em], bu = beta_u[em];

    // ================= PASS A via per-channel l-statistics =================
    // U1[p][q] = sum l[p,q];  U2: diag (qq) + cross products per p.
    // Warp-uniform work mapping: wi = k*14+warp -> channel wi>>2, sub wi&3.
    for (int k = 0; k < 3; k++) {
        const int wi = k*14 + (tid >> 5);
        if (wi < 32) {
            const int cl = wi >> 2, sub = wi & 3;
            const int pi = sub*32 + lane;        // pair index within channel
            const bool act = pi < (SSZ/2);
            const int s = act ? 2*pi : 0;
            const float* lbase = l + ((size_t)(n*CC + crank*CPB + cl)*16)*SSZ + s;
            float2 lf[16];
#pragma unroll
            for (int i = 0; i < 16; i++) {
                int d = 4*((i>>2) ^ Lp) + ((i&2) ^ (L0<<1)) + (i&1);
                float2 t = *(const float2*)(lbase + d*SSZ);
                lf[i] = act ? t : make_float2(0.f, 0.f);
            }
            float U1s[16], sq[16];
#pragma unroll
            for (int i = 0; i < 16; i++) {
                U1s[i] = lf[i].x + lf[i].y;
                sq[i]  = fmaf(lf[i].x, lf[i].x, lf[i].y*lf[i].y);
            }
            float p01r[4], p23r[4], p02v[4], p13v[4], p03r[4], p12r[4];
#pragma unroll
            for (int gg = 0; gg < 4; gg++) {
                const float2* b = lf + 4*gg;
                p01r[gg] = fmaf(b[0].x, b[1].x, b[0].y*b[1].y);
                p23r[gg] = fmaf(b[2].x, b[3].x, b[2].y*b[3].y);
                p02v[gg] = fmaf(b[0].x, b[2].x, b[0].y*b[2].y);
                p13v[gg] = fmaf(b[1].x, b[3].x, b[1].y*b[3].y);
                p03r[gg] = fmaf(b[0].x, b[3].x, b[0].y*b[3].y);
                p12r[gg] = fmaf(b[1].x, b[2].x, b[1].y*b[2].y);
            }
            u64 y1[8], y1b[8], y2[8], y2b[8];
#pragma unroll
            for (int j = 0; j < 8; j++) {
                const int gg = CJ(j), jj = j >> 2;
                y1 [j] = pk2(U1s[4*gg+2*jj], U1s[4*gg+2*jj+1]);
                y1b[j] = pk2(sq [4*gg+2*jj], sq [4*gg+2*jj+1]);
                u64 k0  = L0 ? pk2(p23r[gg], p01r[gg]) : pk2(p01r[gg], p23r[gg]);
                u64 k1  = pk2(p02v[gg], p13v[gg]);
                u64 k0b = L0 ? pk2(p12r[gg], p03r[gg]) : pk2(p03r[gg], p12r[gg]);
                const int kb = L0 ^ jj;
                y2 [j] = kb ? k1   : k0;
                y2b[j] = kb ? 0ull : k0b;
            }
            reduce8x2(y1, y2b[0] == y2b[0] ? y1b : y1b);  // (keep simple: two calls below)
            reduce8x2(y2, y2b);
            const int sidx = ((lane>>3)&1)*16 + 2*(lane&7) + ((lane>>4)&1);
            float lo, hi;
            u64 m1 = ((lane>>3)&1) ? y1b[0] : y1[0];
            upk(m1, lo, hi);
            atomicAdd(&Ush[cl*64 + sidx], ((lane>>4)&1) ? hi : lo);
            u64 m2 = ((lane>>3)&1) ? y2b[0] : y2[0];
            upk(m2, lo, hi);
            atomicAdd(&Ush[cl*64 + 32 + sidx], ((lane>>4)&1) ? hi : lo);
        }
    }
    __syncthreads();

    // ----- contraction: S1/S2 partials for this CTA's 8 channels -----
    if (tid < 160) {
        const int p_ = ed >> 2, r_ = ed & 3;
        float s1 = 0.f, s2 = 0.f;
#pragma unroll
        for (int c = 0; c < CPB; c++) {
            const float* u   = &Ush[c*64];
            const float* wcm = &w_sh[c*160 + em*16];
            float w0 = wcm[r_], w1 = wcm[4+r_], w2 = wcm[8+r_], w3 = wcm[12+r_];
            const float* u1 = u + 4*p_;
            s1 += w0*u1[0] + w1*u1[1] + w2*u1[2] + w3*u1[3];
            const float* dq = u + 16 + 4*p_;
            s2 += w0*w0*dq[0] + w1*w1*dq[1] + w2*w2*dq[2] + w3*w3*dq[3];
            const float* pp = u + 32 + 4*p_;
            float cr = w0*w1*pp[0] + w2*w3*pp[1] + w0*w2*pp[2] + w1*w3*pp[3];
            const float* pv = u + 48 + 4*p_;
            cr += w0*w3*pv[0] + w1*w2*pv[1];
            s2 += 2.f*cr;
        }
        acc1[tid] = s1;
        acc2[tid] = s2;
    }
    __syncthreads();
    cluster_sync_();

    // ----- combine S1/S2 across the 4 CTAs -----
    float S1 = 0.f, S2 = 0.f;
    if (tid < 160) {
#pragma unroll
        for (uint32_t rk = 0; rk < 4; rk++) {
            S1 += cluster_ld_f32(a1addr, rk);
            S2 += cluster_ld_f32(a2addr, rk);
        }
    }
    cluster_sync_();
    if (tid < 160) { acc1[tid] = 0.f; acc2[tid] = 0.f; }

    // ----- epilogue A -----
    if (tid < 160) {
        float gv = g[(n*MM + em)*16 + ed];
        float sig0 = S2 - 2.f*gv*S1 + BBF*gv*gv + EPSF;
        float sl = logf(sig0);
#pragma unroll
        for (int o = 8; o > 0; o >>= 1) sl += __shfl_xor_sync(0xffffffffu, sl, o);

        float a0 = 1.f / (1.f + expf(-(LAM_INIT * (ba - 16.f*bu - 0.5f*sl))));
        float rsum  = BBF * a0 * 0.1f;
        float coeff = (a0 * 0.1f) / (rsum + EPSF);
        float mu    = coeff * S1;
        float sig   = coeff * (S2 - 2.f*mu*S1 + BBF*mu*mu) + EPSF;
        float sl2 = logf(sig);
#pragma unroll
        for (int o = 8; o > 0; o >>= 1) sl2 += __shfl_xor_sync(0xffffffffu, sl2, o);

        float logit = LAM_ROUT * (ba - rsum * (16.f*bu + 0.5f*sl2));
        float a1 = 1.f / (1.f + expf(-logit));

        float i2  = 0.5f / sig;
        float cst = mu*mu*i2;
#pragma unroll
        for (int o = 8; o > 0; o >>= 1) cst += __shfl_xor_sync(0xffffffffu, cst, o);

        ep_sh[em*32 + (ed>>1)*4 +     (ed&1)] = i2;
        ep_sh[em*32 + (ed>>1)*4 + 2 + (ed&1)] = -(mu / sig);
        if (ed == 0) {
            a_sh[em] = a1;
            K_sh[em] = -0.5f*sl2 - 8.f*LN2PI + logf(a1) - cst;
        }
    }
    __syncthreads();

    // ================= routing iterations 1 and 2 =================
    for (int it = 0; it < 2; it++) {
#pragma unroll
        for (int k = 0; k < NITER; k++) {
            const int pr = tid + k*THREADS;
            const bool act = pr < NPAIRS;
            const int prc = act ? pr : 0;
            const int cl = prc / (SSZ/2), s = 2*prc - cl*SSZ;
            const float* lbase = l + ((size_t)(n*CC + crank*CPB + cl)*16)*SSZ + s;
            float2 lf[16];
#pragma unroll
            for (int i = 0; i < 16; i++) {
                int d = 4*((i>>2) ^ Lp) + (i&3);
                float2 t = *(const float2*)(lbase + d*SSZ);
                lf[i] = act ? t : make_float2(0.f, 0.f);
            }

            // ---- E-step: both items ----
            float lnapA[10], lnapB[10];
#pragma unroll
            for (int m = 0; m < MM; m++) {
                const float* wm = &w_sh[cl*160 + m*16];
                u64 wA[4], wB[4];
#pragma unroll
                for (int q = 0; q < 4; q++) {
                    wA[q] = *(const u64*)(wm + 4*q + 2*L0);
                    wB[q] = *(const u64*)(wm + 4*q + 2*(L0^1));
                }
                u64 qA = 0ull, qB = 0ull;
#pragma unroll
                for (int j = 0; j < 8; j++) {
                    const int cj = CJ(j);
                    const u64* wc = (j < 4) ? wA : wB;
                    const int u = L7 ^ BR3(j);
                    ulonglong2 ep = *(const ulonglong2*)&ep_sh[m*32 + u*4];
                    u64 vA = fma2(bc2(lf[4*cj].x),   wc[0],
                             fma2(bc2(lf[4*cj+1].x), wc[1],
                             fma2(bc2(lf[4*cj+2].x), wc[2],
                             mul2(bc2(lf[4*cj+3].x), wc[3]))));
                    u64 vB = fma2(bc2(lf[4*cj].y),   wc[0],
                             fma2(bc2(lf[4*cj+1].y), wc[1],
                             fma2(bc2(lf[4*cj+2].y), wc[2],
                             mul2(bc2(lf[4*cj+3].y), wc[3]))));
                    qA = fma2(vA, fma2(vA, ep.x, ep.y), qA);
                    qB = fma2(vB, fma2(vB, ep.x, ep.y), qB);
                }
                float ql, qh;
                upk(qA, ql, qh); lnapA[m] = K_sh[m] - (ql + qh);
                upk(qB, ql, qh); lnapB[m] = K_sh[m] - (ql + qh);
            }

            // stable softmax * a, both items; inactive threads masked to 0
            {
                float mxA = lnapA[0], mxB = lnapB[0];
#pragma unroll
                for (int m = 1; m < MM; m++) { mxA = fmaxf(mxA, lnapA[m]); mxB = fmaxf(mxB, lnapB[m]); }
                float dA = 0.f, dB = 0.f;
#pragma unroll
                for (int m = 0; m < MM; m++) {
                    lnapA[m] = __expf(lnapA[m] - mxA); dA += lnapA[m];
                    lnapB[m] = __expf(lnapB[m] - mxB); dB += lnapB[m];
                }
                float sA = act ? (1.f / dA) : 0.f;
                float sB = act ? (1.f / dB) : 0.f;
#pragma unroll
                for (int m = 0; m < MM; m++) {
                    lnapA[m] = lnapA[m] * sA * a_sh[m];
                    lnapB[m] = lnapB[m] * sB * a_sh[m];
                }
            }

            // ---- M-step statistics: pair-accumulated before reduction ----
#pragma unroll
            for (int m = 0; m < MM; m++) {
                const float* wm = &w_sh[cl*160 + m*16];
                u64 wA[4], wB[4];
#pragma unroll
                for (int q = 0; q < 4; q++) {
                    wA[q] = *(const u64*)(wm + 4*q + 2*L0);
                    wB[q] = *(const u64*)(wm + 4*q + 2*(L0^1));
                }
                u64 rA = bc2(lnapA[m]), rB = bc2(lnapB[m]);
                u64 yV[8], yV2[8];
#pragma unroll
                for (int j = 0; j < 8; j++) {
                    const int cj = CJ(j);
                    const u64* wc = (j < 4) ? wA : wB;
                    u64 vA = fma2(bc2(lf[4*cj].x),   wc[0],
                             fma2(bc2(lf[4*cj+1].x), wc[1],
                             fma2(bc2(lf[4*cj+2].x), wc[2],
                             mul2(bc2(lf[4*cj+3].x), wc[3]))));
                    u64 vB = fma2(bc2(lf[4*cj].y),   wc[0],
                             fma2(bc2(lf[4*cj+1].y), wc[1],
                             fma2(bc2(lf[4*cj+2].y), wc[2],
                             mul2(bc2(lf[4*cj+3].y), wc[3]))));
                    u64 cA = mul2(rA, vA), cB = mul2(rB, vB);
                    yV [j] = add2(cA, cB);
                    yV2[j] = add2(mul2(cA, vA), mul2(cB, vB));
                }
                reduce8x2(yV, yV2);
                u64 mine = ((lane>>3)&1) ? yV2[0] : yV[0];
                float lo, hi; upk(mine, lo, hi);
                atomicAdd(accp + m*16, ((lane>>4)&1) ? hi : lo);
            }
            // R sums (pair-summed)
            {
                float y[16];
#pragma unroll
                for (int m = 0; m < MM; m++) y[m] = lnapA[m] + lnapB[m];
#pragma unroll
                for (int m = MM; m < 16; m++) y[m] = 0.f;
                float val = reduce16_to_lane(y, lane);
                int idx4 = bitrev4(lane & 15);
                if (lane < 16 && idx4 < MM) atomicAdd(&accR[idx4], val);
            }
        }
        __syncthreads();
        cluster_sync_();

        // combine A1/A2/R across CTAs
        float A1 = 0.f, A2 = 0.f, R = 0.f;
        if (tid < 160) {
#pragma unroll
            for (uint32_t rk = 0; rk < 4; rk++) {
                A1 += cluster_ld_f32(a1addr, rk);
                A2 += cluster_ld_f32(a2addr, rk);
            }
        }
        if (tid < 16) {
#pragma unroll
            for (uint32_t rk = 0; rk < 4; rk++) R += cluster_ld_f32(aRaddr, rk);
        }
        cluster_sync_();
        if (tid < 160) { acc1[tid] = 0.f; acc2[tid] = 0.f; }
        if (tid < 16)  accR[tid] = 0.f;
        if (tid < 10)  Rtot[tid] = R;
        __syncthreads();

        if (tid < 160) {
            float Rm  = Rtot[em];
            float inv = 1.f / (Rm + EPSF);
            float mu  = A1 * inv;
            float sig = (A2 - 2.f*mu*A1 + mu*mu*Rm) * inv + EPSF;
            float sl  = logf(sig);
#pragma unroll
            for (int o = 8; o > 0; o >>= 1) sl += __shfl_xor_sync(0xffffffffu, sl, o);

            float logit = LAM_ROUT * (ba - Rm * (16.f*bu + 0.5f*sl));
            float a = 1.f / (1.f + expf(-logit));

            if (it == 0) {
                float i2  = 0.5f / sig;
                float cst = mu*mu*i2;
#pragma unroll
                for (int o = 8; o > 0; o >>= 1) cst += __shfl_xor_sync(0xffffffffu, cst, o);
                ep_sh[em*32 + (ed>>1)*4 +     (ed&1)] = i2;
                ep_sh[em*32 + (ed>>1)*4 + 2 + (ed&1)] = -(mu / sig);
                if (ed == 0) {
                    a_sh[em] = a;
                    K_sh[em] = -0.5f*sl - 8.f*LN2PI + logf(a) - cst;
                }
            } else if (crank == 0) {
                out[NN*MM + n*160 + tid] = mu;          // mu block (N, M, 16)
                if (ed == 0) out[n*MM + em] = a;        // a_out block (N, M)
            }
        }
        __syncthreads();
    }
}

extern "C" void kernel_launch(void* const* d_in, const int* in_sizes, int n_in,
                              void* d_out, int out_size)
{
    const float* l      = (const float*)d_in[0];
    const float* g      = (const float*)d_in[1];
    const float* weight = (const float*)d_in[2];
    const float* beta_a = (const float*)d_in[3];
    const float* beta_u = (const float*)d_in[4];
    float* out = (float*)d_out;

    k_mega<<<NN*4, THREADS>>>(l, g, weight, beta_a, beta_u, out);

    (void)in_sizes; (void)n_in; (void)out_size;
}

// round 11
// speedup vs baseline: 6.7567x; 1.0940x over previous
#include <cuda_runtime.h>
#include <math.h>
#include <stdint.h>

#define NN 32
#define CC 32
#define MM 10
#define SSZ 196
#define CPB 8                 // channels per CTA
#define ITEMS (CPB*SSZ)       // 1568 items per CTA
#define NPAIRS (ITEMS/2)      // 784 item-pairs per CTA
#define THREADS 512
#define NITER ((NPAIRS + THREADS - 1) / THREADS)   // 2, uniform for all threads
#define BBF 6272.0f
#define EPSF 1e-6f
#define LAM_INIT 0.001f
#define LAM_ROUT 0.001f
#define LN2PI 1.8378770664093453f

typedef unsigned long long u64;

// ---- packed f32x2 helpers ----
__device__ __forceinline__ u64 pk2(float lo, float hi) {
    u64 r; asm("mov.b64 %0, {%1,%2};" : "=l"(r) : "f"(lo), "f"(hi)); return r;
}
__device__ __forceinline__ u64 bc2(float x) { return pk2(x, x); }
__device__ __forceinline__ void upk(u64 v, float& lo, float& hi) {
    asm("mov.b64 {%0,%1}, %2;" : "=f"(lo), "=f"(hi) : "l"(v));
}
__device__ __forceinline__ u64 fma2(u64 a, u64 b, u64 c) {
    u64 d; asm("fma.rn.f32x2 %0, %1, %2, %3;" : "=l"(d) : "l"(a), "l"(b), "l"(c)); return d;
}
__device__ __forceinline__ u64 mul2(u64 a, u64 b) {
    u64 d; asm("mul.rn.f32x2 %0, %1, %2;" : "=l"(d) : "l"(a), "l"(b)); return d;
}
__device__ __forceinline__ u64 add2(u64 a, u64 b) {
    u64 d; asm("add.rn.f32x2 %0, %1, %2;" : "=l"(d) : "l"(a), "l"(b)); return d;
}
__device__ __forceinline__ u64 shx2(u64 v, int d) {
    return __shfl_xor_sync(0xffffffffu, v, d);
}

// ---- cluster helpers ----
__device__ __forceinline__ void cluster_sync_() {
    asm volatile("barrier.cluster.arrive.aligned;" ::: "memory");
    asm volatile("barrier.cluster.wait.aligned;"   ::: "memory");
}
__device__ __forceinline__ uint32_t smem_u32(const void* p) {
    uint32_t a;
    asm("{ .reg .u64 t; cvta.to.shared.u64 t, %1; cvt.u32.u64 %0, t; }" : "=r"(a) : "l"(p));
    return a;
}
__device__ __forceinline__ float cluster_ld_f32(uint32_t laddr, uint32_t rank) {
    uint32_t ra; float v;
    asm("mapa.shared::cluster.u32 %0, %1, %2;" : "=r"(ra) : "r"(laddr), "r"(rank));
    asm volatile("ld.shared::cluster.f32 %0, [%1];" : "=f"(v) : "r"(ra) : "memory");
    return v;
}

__device__ __forceinline__ int bitrev4(int x) {
    return ((x&1)<<3) | (((x>>1)&1)<<2) | (((x>>2)&1)<<1) | ((x>>3)&1);
}

// SEL-free permuted dual reduction with merged tail (R11).
// Lane L placed slot (L&7)^bitrev3(j) at position j for both arrays.
// Stages xor1/2/4 reduce within 8-lane groups; at xor8 each lane keeps ITS
// array (yB if bit3 else yA) and folds in the partner's copy; at xor16 a
// scalar shuffle exchanges only the needed lo/hi (bit4) component.
// Returns the single scalar this lane owns: array = bit3, slot = lane&7,
// component = bit4 — identical ownership map to the old reduce8x2 tail.
__device__ __forceinline__ float reduce8x2r(u64 (&yA)[8], u64 (&yB)[8], int lane)
{
#pragma unroll
    for (int j = 0; j < 4; j++) {
        yA[j] = add2(yA[j], shx2(yA[j+4], 1));
        yB[j] = add2(yB[j], shx2(yB[j+4], 1));
    }
#pragma unroll
    for (int j = 0; j < 2; j++) {
        yA[j] = add2(yA[j], shx2(yA[j+2], 2));
        yB[j] = add2(yB[j], shx2(yB[j+2], 2));
    }
    yA[0] = add2(yA[0], shx2(yA[1], 4));
    yB[0] = add2(yB[0], shx2(yB[1], 4));
    // xor8: merge arrays — keep own (bit3), send the other
    u64 keep = (lane & 8) ? yB[0] : yA[0];
    u64 send = (lane & 8) ? yA[0] : yB[0];
    u64 z = add2(keep, shx2(send, 8));
    // xor16: scalar exchange of the needed component (bit4)
    float lo, hi; upk(z, lo, hi);
    float kp = (lane & 16) ? hi : lo;
    float sd = (lane & 16) ? lo : hi;
    return kp + __shfl_xor_sync(0xffffffffu, sd, 16);
}

// 16 scalars across 32 lanes (R); lane owns bitrev4(lane&15).
__device__ __forceinline__ float reduce16_to_lane(float (&y)[16], int lane)
{
#pragma unroll
    for (int j = 0; j < 8; j++) {
        bool up = lane & 1;
        float s = up ? y[j] : y[j+8];
        float k = up ? y[j+8] : y[j];
        y[j] = k + __shfl_xor_sync(0xffffffffu, s, 1);
    }
#pragma unroll
    for (int j = 0; j < 4; j++) {
        bool up = lane & 2;
        float s = up ? y[j] : y[j+4];
        float k = up ? y[j+4] : y[j];
        y[j] = k + __shfl_xor_sync(0xffffffffu, s, 2);
    }
#pragma unroll
    for (int j = 0; j < 2; j++) {
        bool up = lane & 4;
        float s = up ? y[j] : y[j+2];
        float k = up ? y[j+2] : y[j];
        y[j] = k + __shfl_xor_sync(0xffffffffu, s, 4);
    }
    {
        bool up = lane & 8;
        float s = up ? y[0] : y[1];
        float k = up ? y[1] : y[0];
        y[0] = k + __shfl_xor_sync(0xffffffffu, s, 8);
    }
    y[0] += __shfl_xor_sync(0xffffffffu, y[0], 16);
    return y[0];
}

#define CJ(j)  ((((j)&1)<<1) | (((j)>>1)&1))
#define BR3(j) (((((j)&1))<<2) | ((j)&2) | (((j)>>2)&1))

// ======================= the single fused kernel =======================
__global__ __cluster_dims__(4,1,1) __launch_bounds__(THREADS,1)
void k_mega(const float* __restrict__ l, const float* __restrict__ g,
            const float* __restrict__ w, const float* __restrict__ beta_a,
            const float* __restrict__ beta_u, float* __restrict__ out)
{
    __shared__ alignas(16) float w_sh[CPB*160];
    __shared__ alignas(16) float ep_sh[MM*32];   // [m][u][i2lo,i2hi,mu2nlo,mu2nhi]
    __shared__ alignas(16) float Ush[CPB*64];    // per-channel l-statistics (pass A)
    __shared__ float K_sh[10], a_sh[10], Rtot[10];
    __shared__ float acc1[160], acc2[160], accR[16];

    const int tid = threadIdx.x, lane = tid & 31;
    const int crank = blockIdx.x & 3;
    const int n     = blockIdx.x >> 2;

    const int Lp = (lane >> 1) & 3;
    const int L0 = lane & 1;
    const int L7 = lane & 7;

    for (int i = tid; i < CPB*160; i += THREADS)
        w_sh[i] = w[(crank*CPB)*160 + i];
    for (int i = tid; i < CPB*64; i += THREADS)
        Ush[i] = 0.f;
    if (tid < 160) { acc1[tid] = 0.f; acc2[tid] = 0.f; }
    if (tid < 16)  accR[tid] = 0.f;
    __syncthreads();

    float* accp = (((lane>>3)&1) ? acc2 : acc1) + 4*Lp + 2*L0 + ((lane>>4)&1);

    const uint32_t a1addr = smem_u32(&acc1[tid < 160 ? tid : 0]);
    const uint32_t a2addr = smem_u32(&acc2[tid < 160 ? tid : 0]);
    const uint32_t aRaddr = smem_u32(&accR[tid < 16  ? tid : 0]);

    const int em = (tid < 160) ? (tid >> 4) : 0;
    const int ed = tid & 15;
    const float ba = beta_a[em], bu = beta_u[em];

    // ================= PASS A via per-channel l-statistics =================
    // Warp-uniform work mapping: wi = k*16+warp in [0,32) -> channel wi>>2, sub wi&3.
    for (int k = 0; k < 2; k++) {
        const int wi = k*16 + (tid >> 5);
        {
            const int cl = wi >> 2, sub = wi & 3;
            const int pi = sub*32 + lane;        // pair index within channel
            const bool act = pi < (SSZ/2);
            const int s = act ? 2*pi : 0;
            const float* lbase = l + ((size_t)(n*CC + crank*CPB + cl)*16)*SSZ + s;
            float2 lf[16];
#pragma unroll
            for (int i = 0; i < 16; i++) {
                int d = 4*((i>>2) ^ Lp) + ((i&2) ^ (L0<<1)) + (i&1);
                float2 t = *(const float2*)(lbase + d*SSZ);
                lf[i] = act ? t : make_float2(0.f, 0.f);
            }
            float U1s[16], sq[16];
#pragma unroll
            for (int i = 0; i < 16; i++) {
                U1s[i] = lf[i].x + lf[i].y;
                sq[i]  = fmaf(lf[i].x, lf[i].x, lf[i].y*lf[i].y);
            }
            float p01r[4], p23r[4], p02v[4], p13v[4], p03r[4], p12r[4];
#pragma unroll
            for (int gg = 0; gg < 4; gg++) {
                const float2* b = lf + 4*gg;
                p01r[gg] = fmaf(b[0].x, b[1].x, b[0].y*b[1].y);
                p23r[gg] = fmaf(b[2].x, b[3].x, b[2].y*b[3].y);
                p02v[gg] = fmaf(b[0].x, b[2].x, b[0].y*b[2].y);
                p13v[gg] = fmaf(b[1].x, b[3].x, b[1].y*b[3].y);
                p03r[gg] = fmaf(b[0].x, b[3].x, b[0].y*b[3].y);
                p12r[gg] = fmaf(b[1].x, b[2].x, b[1].y*b[2].y);
            }
            u64 y1[8], y1b[8], y2[8], y2b[8];
#pragma unroll
            for (int j = 0; j < 8; j++) {
                const int gg = CJ(j), jj = j >> 2;
                y1 [j] = pk2(U1s[4*gg+2*jj], U1s[4*gg+2*jj+1]);
                y1b[j] = pk2(sq [4*gg+2*jj], sq [4*gg+2*jj+1]);
                u64 k0  = L0 ? pk2(p23r[gg], p01r[gg]) : pk2(p01r[gg], p23r[gg]);
                u64 k1  = pk2(p02v[gg], p13v[gg]);
                u64 k0b = L0 ? pk2(p12r[gg], p03r[gg]) : pk2(p03r[gg], p12r[gg]);
                const int kb = L0 ^ jj;
                y2 [j] = kb ? k1   : k0;
                y2b[j] = kb ? 0ull : k0b;
            }
            const int sidx = ((lane>>3)&1)*16 + 2*(lane&7) + ((lane>>4)&1);
            float r1 = reduce8x2r(y1, y1b, lane);
            atomicAdd(&Ush[cl*64 + sidx], r1);
            float r2 = reduce8x2r(y2, y2b, lane);
            atomicAdd(&Ush[cl*64 + 32 + sidx], r2);
        }
    }
    __syncthreads();

    // ----- contraction: S1/S2 partials for this CTA's 8 channels -----
    if (tid < 160) {
        const int p_ = ed >> 2, r_ = ed & 3;
        float s1 = 0.f, s2 = 0.f;
#pragma unroll
        for (int c = 0; c < CPB; c++) {
            const float* u   = &Ush[c*64];
            const float* wcm = &w_sh[c*160 + em*16];
            float w0 = wcm[r_], w1 = wcm[4+r_], w2 = wcm[8+r_], w3 = wcm[12+r_];
            const float* u1 = u + 4*p_;
            s1 += w0*u1[0] + w1*u1[1] + w2*u1[2] + w3*u1[3];
            const float* dq = u + 16 + 4*p_;
            s2 += w0*w0*dq[0] + w1*w1*dq[1] + w2*w2*dq[2] + w3*w3*dq[3];
            const float* pp = u + 32 + 4*p_;
            float cr = w0*w1*pp[0] + w2*w3*pp[1] + w0*w2*pp[2] + w1*w3*pp[3];
            const float* pv = u + 48 + 4*p_;
            cr += w0*w3*pv[0] + w1*w2*pv[1];
            s2 += 2.f*cr;
        }
        acc1[tid] = s1;
        acc2[tid] = s2;
    }
    __syncthreads();
    cluster_sync_();

    // ----- combine S1/S2 across the 4 CTAs -----
    float S1 = 0.f, S2 = 0.f;
    if (tid < 160) {
#pragma unroll
        for (uint32_t rk = 0; rk < 4; rk++) {
            S1 += cluster_ld_f32(a1addr, rk);
            S2 += cluster_ld_f32(a2addr, rk);
        }
    }
    cluster_sync_();
    if (tid < 160) { acc1[tid] = 0.f; acc2[tid] = 0.f; }

    // ----- epilogue A -----
    if (tid < 160) {
        float gv = g[(n*MM + em)*16 + ed];
        float sig0 = S2 - 2.f*gv*S1 + BBF*gv*gv + EPSF;
        float sl = logf(sig0);
#pragma unroll
        for (int o = 8; o > 0; o >>= 1) sl += __shfl_xor_sync(0xffffffffu, sl, o);

        float a0 = 1.f / (1.f + expf(-(LAM_INIT * (ba - 16.f*bu - 0.5f*sl))));
        float rsum  = BBF * a0 * 0.1f;
        float coeff = (a0 * 0.1f) / (rsum + EPSF);
        float mu    = coeff * S1;
        float sig   = coeff * (S2 - 2.f*mu*S1 + BBF*mu*mu) + EPSF;
        float sl2 = logf(sig);
#pragma unroll
        for (int o = 8; o > 0; o >>= 1) sl2 += __shfl_xor_sync(0xffffffffu, sl2, o);

        float logit = LAM_ROUT * (ba - rsum * (16.f*bu + 0.5f*sl2));
        float a1 = 1.f / (1.f + expf(-logit));

        float i2  = 0.5f / sig;
        float cst = mu*mu*i2;
#pragma unroll
        for (int o = 8; o > 0; o >>= 1) cst += __shfl_xor_sync(0xffffffffu, cst, o);

        ep_sh[em*32 + (ed>>1)*4 +     (ed&1)] = i2;
        ep_sh[em*32 + (ed>>1)*4 + 2 + (ed&1)] = -(mu / sig);
        if (ed == 0) {
            a_sh[em] = a1;
            K_sh[em] = -0.5f*sl2 - 8.f*LN2PI + logf(a1) - cst;
        }
    }
    __syncthreads();

    // ================= routing iterations 1 and 2 =================
    for (int it = 0; it < 2; it++) {
#pragma unroll
        for (int k = 0; k < NITER; k++) {
            // warp-uniform skip of fully-inactive warps (no barriers inside body)
            if ((tid & ~31) + k*THREADS >= NPAIRS) continue;
            const int pr = tid + k*THREADS;
            const bool act = pr < NPAIRS;
            const int prc = act ? pr : 0;
            const int cl = prc / (SSZ/2), s = 2*prc - cl*SSZ;
            const float* lbase = l + ((size_t)(n*CC + crank*CPB + cl)*16)*SSZ + s;
            float2 lf[16];
#pragma unroll
            for (int i = 0; i < 16; i++) {
                int d = 4*((i>>2) ^ Lp) + (i&3);
                float2 t = *(const float2*)(lbase + d*SSZ);
                lf[i] = act ? t : make_float2(0.f, 0.f);
            }

            // ---- E-step: both items ----
            float lnapA[10], lnapB[10];
#pragma unroll
            for (int m = 0; m < MM; m++) {
                const float* wm = &w_sh[cl*160 + m*16];
                u64 wA[4], wB[4];
#pragma unroll
                for (int q = 0; q < 4; q++) {
                    wA[q] = *(const u64*)(wm + 4*q + 2*L0);
                    wB[q] = *(const u64*)(wm + 4*q + 2*(L0^1));
                }
                u64 qA = 0ull, qB = 0ull;
#pragma unroll
                for (int j = 0; j < 8; j++) {
                    const int cj = CJ(j);
                    const u64* wc = (j < 4) ? wA : wB;
                    const int u = L7 ^ BR3(j);
                    ulonglong2 ep = *(const ulonglong2*)&ep_sh[m*32 + u*4];
                    u64 vA = fma2(bc2(lf[4*cj].x),   wc[0],
                             fma2(bc2(lf[4*cj+1].x), wc[1],
                             fma2(bc2(lf[4*cj+2].x), wc[2],
                             mul2(bc2(lf[4*cj+3].x), wc[3]))));
                    u64 vB = fma2(bc2(lf[4*cj].y),   wc[0],
                             fma2(bc2(lf[4*cj+1].y), wc[1],
                             fma2(bc2(lf[4*cj+2].y), wc[2],
                             mul2(bc2(lf[4*cj+3].y), wc[3]))));
                    qA = fma2(vA, fma2(vA, ep.x, ep.y), qA);
                    qB = fma2(vB, fma2(vB, ep.x, ep.y), qB);
                }
                float ql, qh;
                upk(qA, ql, qh); lnapA[m] = K_sh[m] - (ql + qh);
                upk(qB, ql, qh); lnapB[m] = K_sh[m] - (ql + qh);
            }

            // stable softmax * a, both items; inactive threads masked to 0
            {
                float mxA = lnapA[0], mxB = lnapB[0];
#pragma unroll
                for (int m = 1; m < MM; m++) { mxA = fmaxf(mxA, lnapA[m]); mxB = fmaxf(mxB, lnapB[m]); }
                float dA = 0.f, dB = 0.f;
#pragma unroll
                for (int m = 0; m < MM; m++) {
                    lnapA[m] = __expf(lnapA[m] - mxA); dA += lnapA[m];
                    lnapB[m] = __expf(lnapB[m] - mxB); dB += lnapB[m];
                }
                float sA = act ? (1.f / dA) : 0.f;
                float sB = act ? (1.f / dB) : 0.f;
#pragma unroll
                for (int m = 0; m < MM; m++) {
                    lnapA[m] = lnapA[m] * sA * a_sh[m];
                    lnapB[m] = lnapB[m] * sB * a_sh[m];
                }
            }

            // ---- M-step statistics: pair-accumulated before reduction ----
#pragma unroll
            for (int m = 0; m < MM; m++) {
                const float* wm = &w_sh[cl*160 + m*16];
                u64 wA[4], wB[4];
#pragma unroll
                for (int q = 0; q < 4; q++) {
                    wA[q] = *(const u64*)(wm + 4*q + 2*L0);
                    wB[q] = *(const u64*)(wm + 4*q + 2*(L0^1));
                }
                u64 rA = bc2(lnapA[m]), rB = bc2(lnapB[m]);
                u64 yV[8], yV2[8];
#pragma unroll
                for (int j = 0; j < 8; j++) {
                    const int cj = CJ(j);
                    const u64* wc = (j < 4) ? wA : wB;
                    u64 vA = fma2(bc2(lf[4*cj].x),   wc[0],
                             fma2(bc2(lf[4*cj+1].x), wc[1],
                             fma2(bc2(lf[4*cj+2].x), wc[2],
                             mul2(bc2(lf[4*cj+3].x), wc[3]))));
                    u64 vB = fma2(bc2(lf[4*cj].y),   wc[0],
                             fma2(bc2(lf[4*cj+1].y), wc[1],
                             fma2(bc2(lf[4*cj+2].y), wc[2],
                             mul2(bc2(lf[4*cj+3].y), wc[3]))));
                    u64 cA = mul2(rA, vA), cB = mul2(rB, vB);
                    yV [j] = add2(cA, cB);
                    yV2[j] = add2(mul2(cA, vA), mul2(cB, vB));
                }
                float res = reduce8x2r(yV, yV2, lane);
                atomicAdd(accp + m*16, res);
            }
            // R sums (pair-summed)
            {
                float y[16];
#pragma unroll
                for (int m = 0; m < MM; m++) y[m] = lnapA[m] + lnapB[m];
#pragma unroll
                for (int m = MM; m < 16; m++) y[m] = 0.f;
                float val = reduce16_to_lane(y, lane);
                int idx4 = bitrev4(lane & 15);
                if (lane < 16 && idx4 < MM) atomicAdd(&accR[idx4], val);
            }
        }
        __syncthreads();
        cluster_sync_();

        // combine A1/A2/R across CTAs
        float A1 = 0.f, A2 = 0.f, R = 0.f;
        if (tid < 160) {
#pragma unroll
            for (uint32_t rk = 0; rk < 4; rk++) {
                A1 += cluster_ld_f32(a1addr, rk);
                A2 += cluster_ld_f32(a2addr, rk);
            }
        }
        if (tid < 16) {
#pragma unroll
            for (uint32_t rk = 0; rk < 4; rk++) R += cluster_ld_f32(aRaddr, rk);
        }
        cluster_sync_();
        if (tid < 160) { acc1[tid] = 0.f; acc2[tid] = 0.f; }
        if (tid < 16)  accR[tid] = 0.f;
        if (tid < 10)  Rtot[tid] = R;
        __syncthreads();

        if (tid < 160) {
            float Rm  = Rtot[em];
            float inv = 1.f / (Rm + EPSF);
            float mu  = A1 * inv;
            float sig = (A2 - 2.f*mu*A1 + mu*mu*Rm) * inv + EPSF;
            float sl  = logf(sig);
#pragma unroll
            for (int o = 8; o > 0; o >>= 1) sl += __shfl_xor_sync(0xffffffffu, sl, o);

            float logit = LAM_ROUT * (ba - Rm * (16.f*bu + 0.5f*sl));
            float a = 1.f / (1.f + expf(-logit));

            if (it == 0) {
                float i2  = 0.5f / sig;
                float cst = mu*mu*i2;
#pragma unroll
                for (int o = 8; o > 0; o >>= 1) cst += __shfl_xor_sync(0xffffffffu, cst, o);
                ep_sh[em*32 + (ed>>1)*4 +     (ed&1)] = i2;
                ep_sh[em*32 + (ed>>1)*4 + 2 + (ed&1)] = -(mu / sig);
                if (ed == 0) {
                    a_sh[em] = a;
                    K_sh[em] = -0.5f*sl - 8.f*LN2PI + logf(a) - cst;
                }
            } else if (crank == 0) {
                out[NN*MM + n*160 + tid] = mu;          // mu block (N, M, 16)
                if (ed == 0) out[n*MM + em] = a;        // a_out block (N, M)
            }
        }
        __syncthreads();
    }
}

extern "C" void kernel_launch(void* const* d_in, const int* in_sizes, int n_in,
                              void* d_out, int out_size)
{
    const float* l      = (const float*)d_in[0];
    const float* g      = (const float*)d_in[1];
    const float* weight = (const float*)d_in[2];
    const float* beta_a = (const float*)d_in[3];
    const float* beta_u = (const float*)d_in[4];
    float* out = (float*)d_out;

    k_mega<<<NN*4, THREADS>>>(l, g, weight, beta_a, beta_u, out);

    (void)in_sizes; (void)n_in; (void)out_size;
}